// round 7
// baseline (speedup 1.0000x reference)
#include <cuda_runtime.h>
#include <cuda_fp16.h>

#define IN_DIM 128
#define HEADS 8
#define ODIM 32
#define HID 256            // HEADS*ODIM
#define NEG 0.2f
#define NMAX 50000
#define EMAX 800000

// ---------------- device scratch (static: no allocation allowed) -------------
__device__ __half g_hh[NMAX * HID];      // 25.6 MB (fp16 messages)
__device__ float  g_asrc[NMAX * HEADS];
__device__ float  g_adst[NMAX * HEADS];
__device__ int    g_deg[NMAX];
__device__ int    g_cur[NMAX];
__device__ int    g_off[NMAX + 1];
__device__ int    g_csrc[EMAX];
__device__ int    g_bsum[256];
__device__ int    g_bbase[256];

// ---------------- cp.async helper --------------------------------------------
__device__ __forceinline__ void cp16(void* dst, const void* src, bool pred) {
    unsigned d = (unsigned)__cvta_generic_to_shared(dst);
    int sz = pred ? 16 : 0;
    asm volatile("cp.async.cg.shared.global [%0], [%1], 16, %2;"
                 :: "r"(d), "l"(src), "r"(sz) : "memory");
}

// ---------------- zero -------------------------------------------------------
__global__ void zero_kernel(int n) {
    int i = blockIdx.x * blockDim.x + threadIdx.x;
    if (i < n) { g_deg[i] = 0; g_cur[i] = 0; }
}

// ---------------- fused GEMM + attention dots (cp.async double-buffered) -----
// h = x @ W  (N x 128 @ 128 x 256); epilogue: fp16 h store + fp32 a_src/a_dst.
// Block tile 64 rows x 256 cols, thread tile 8x8, k-tile 32, 2 smem buffers.
__global__ __launch_bounds__(256) void gemm_kernel(
    const float* __restrict__ x, const float* __restrict__ W,
    const float* __restrict__ att_s, const float* __restrict__ att_d, int n)
{
    extern __shared__ float smem[];
    // layout: xs[2][64*32] then ws[2][32*256]
    float* xsb[2] = { smem, smem + 2048 };
    float* wsb[2] = { smem + 4096, smem + 4096 + 8192 };

    int tid = threadIdx.x;
    int tx = tid & 31, ty = tid >> 5;
    int row0 = blockIdx.x * 64;

    float acc[8][8];
    #pragma unroll
    for (int i = 0; i < 8; i++)
        #pragma unroll
        for (int j = 0; j < 8; j++) acc[i][j] = 0.f;

    // ---- issue loads for tile kt into buffer b ----
    auto issue_tile = [&](int kt, int b) {
        float* xs = xsb[b];
        float* ws = wsb[b];
        #pragma unroll
        for (int t = 0; t < 2; t++) {
            int q = tid + t * 256;
            int r = q >> 3, k4 = q & 7;
            int grow = row0 + r;
            cp16(xs + r * 32 + k4 * 4,
                 x + (size_t)grow * IN_DIM + kt * 32 + k4 * 4,
                 grow < n);
        }
        #pragma unroll
        for (int t = 0; t < 8; t++) {
            int q = tid + t * 256;
            int r = q >> 6, c4 = q & 63;
            cp16(ws + r * 256 + c4 * 4,
                 W + (size_t)(kt * 32 + r) * 256 + c4 * 4,
                 true);
        }
        asm volatile("cp.async.commit_group;" ::: "memory");
    };

    issue_tile(0, 0);

    #pragma unroll
    for (int kt = 0; kt < 4; kt++) {
        if (kt < 3) issue_tile(kt + 1, (kt + 1) & 1);
        if (kt < 3) asm volatile("cp.async.wait_group 1;" ::: "memory");
        else        asm volatile("cp.async.wait_group 0;" ::: "memory");
        __syncthreads();

        const float* xs = xsb[kt & 1];
        const float* ws = wsb[kt & 1];
        #pragma unroll 8
        for (int kk = 0; kk < 32; kk++) {
            const float4* wrow = (const float4*)(ws + kk * 256 + tx * 8);
            float4 b0 = wrow[0], b1 = wrow[1];
            float b[8] = {b0.x, b0.y, b0.z, b0.w, b1.x, b1.y, b1.z, b1.w};
            #pragma unroll
            for (int i = 0; i < 8; i++) {
                float a = xs[(ty * 8 + i) * 32 + kk];
                #pragma unroll
                for (int j = 0; j < 8; j++)
                    acc[i][j] = fmaf(a, b[j], acc[i][j]);
            }
        }
        __syncthreads();
    }

    // epilogue: store fp16 h + fused fp32 a_src/a_dst dots
    int col0 = tx * 8;
    float asw[8], adw[8];
    #pragma unroll
    for (int j = 0; j < 8; j++) {
        asw[j] = att_s[col0 + j];
        adw[j] = att_d[col0 + j];
    }
    int head = tx >> 2;

    #pragma unroll
    for (int i = 0; i < 8; i++) {
        int grow = row0 + ty * 8 + i;            // uniform across warp
        if (grow < n) {
            __half2 hv[4];
            #pragma unroll
            for (int p = 0; p < 4; p++)
                hv[p] = __floats2half2_rn(acc[i][2 * p], acc[i][2 * p + 1]);
            *(uint4*)(g_hh + (size_t)grow * HID + col0) = *(uint4*)hv;

            float ss = 0.f, sd = 0.f;
            #pragma unroll
            for (int j = 0; j < 8; j++) {
                ss += acc[i][j] * asw[j];
                sd += acc[i][j] * adw[j];
            }
            ss += __shfl_xor_sync(0xffffffffu, ss, 1);
            ss += __shfl_xor_sync(0xffffffffu, ss, 2);
            sd += __shfl_xor_sync(0xffffffffu, sd, 1);
            sd += __shfl_xor_sync(0xffffffffu, sd, 2);
            if ((tx & 3) == 0) {
                g_asrc[grow * HEADS + head] = ss;
                g_adst[grow * HEADS + head] = sd;
            }
        }
    }
}

// ---------------- degree histogram (edge_index is int32: JAX demotes int64) --
__global__ void deg_kernel(const int* __restrict__ ei, int e, int n) {
    int i = blockIdx.x * blockDim.x + threadIdx.x;
    if (i < e) {
        int d = ei[e + i];   // dst row of edge_index [2, E]
        if ((unsigned)d < (unsigned)n) atomicAdd(&g_deg[d], 1);
    }
}

// ---------------- 3-kernel exclusive scan ------------------------------------
__device__ __forceinline__ int block_scan_incl(int v, int tid) {
    __shared__ int wsum[8];
    int lane = tid & 31, w = tid >> 5;
    int x = v;
    #pragma unroll
    for (int o = 1; o < 32; o <<= 1) {
        int y = __shfl_up_sync(0xffffffffu, x, o);
        if (lane >= o) x += y;
    }
    if (lane == 31) wsum[w] = x;
    __syncthreads();
    if (tid < 8) {
        int y = wsum[tid];
        #pragma unroll
        for (int o = 1; o < 8; o <<= 1) {
            int z = __shfl_up_sync(0xffu, y, o);
            if (tid >= o) y += z;
        }
        wsum[tid] = y;
    }
    __syncthreads();
    int base = (w > 0) ? wsum[w - 1] : 0;
    return x + base;
}

__global__ void scan_a_kernel(int n) {
    int i = blockIdx.x * 256 + threadIdx.x;
    int v = (i < n) ? g_deg[i] : 0;
    int incl = block_scan_incl(v, threadIdx.x);
    if (i < n) g_off[i] = incl - v;
    if (threadIdx.x == 255) g_bsum[blockIdx.x] = incl;
}

__global__ void scan_b_kernel(int nb) {
    int t = threadIdx.x;
    int v = (t < nb) ? g_bsum[t] : 0;
    int incl = block_scan_incl(v, t);
    g_bbase[t] = incl - v;
}

__global__ void scan_c_kernel(int n, int e) {
    int i = blockIdx.x * 256 + threadIdx.x;
    if (i < n) g_off[i] += g_bbase[blockIdx.x];
    if (i == 0) g_off[n] = e;
}

// ---------------- CSR fill ---------------------------------------------------
__global__ void fill_kernel(const int* __restrict__ ei, int e, int n) {
    int i = blockIdx.x * blockDim.x + threadIdx.x;
    if (i < e) {
        int d = ei[e + i];
        int s = ei[i];
        if ((unsigned)d < (unsigned)n) {
            int p = atomicAdd(&g_cur[d], 1);
            g_csrc[g_off[d] + p] = s;
        }
    }
}

// ---------------- single-pass softmax + aggregate ----------------------------
// No max-shift: logits are O(10), exp() safe in fp32, softmax shift-invariant.
__global__ __launch_bounds__(256) void agg_kernel(
    const float* __restrict__ bias, float* __restrict__ out, int n)
{
    int warp = (blockIdx.x * blockDim.x + threadIdx.x) >> 5;
    int lane = threadIdx.x & 31;
    if (warp >= n) return;
    int node = warp;
    int beg = g_off[node], end = g_off[node + 1];

    float adl = (lane < HEADS) ? g_adst[node * HEADS + lane] : 0.f;

    float accx[4], accy[4];
    #pragma unroll
    for (int k = 0; k < 4; k++) { accx[k] = 0.f; accy[k] = 0.f; }
    float s_l = 0.f;               // lane<8: softmax denom for head=lane
    int hsel = lane >> 4;          // 0: even heads, 1: odd heads

    for (int i = beg; i <= end; i++) {
        int src = (i < end) ? g_csrc[i] : node;   // final iter = self loop
        float ex = 0.f;
        if (lane < 8) {
            float ev = g_asrc[src * HEADS + lane] + adl;
            ev = ev > 0.f ? ev : NEG * ev;
            ex = __expf(ev);
            s_l += ex;
        }
        const __half2* hp = (const __half2*)(g_hh + (size_t)src * HID);
        #pragma unroll
        for (int k = 0; k < 4; k++) {
            float exk = __shfl_sync(0xffffffffu, ex, 2 * k + hsel);
            float2 hv = __half22float2(hp[k * 32 + lane]);
            accx[k] = fmaf(exk, hv.x, accx[k]);
            accy[k] = fmaf(exk, hv.y, accy[k]);
        }
    }

    float inv_l = (lane < HEADS) ? __frcp_rn(s_l) : 0.f;
    float resx = 0.f, resy = 0.f;
    #pragma unroll
    for (int k = 0; k < 4; k++) {
        float invk = __shfl_sync(0xffffffffu, inv_l, 2 * k + hsel);
        resx = fmaf(accx[k], invk, resx);
        resy = fmaf(accy[k], invk, resy);
    }
    resx += __shfl_xor_sync(0xffffffffu, resx, 16);
    resy += __shfl_xor_sync(0xffffffffu, resy, 16);
    if (lane < 16) {
        int c = 2 * lane;
        float2 o2 = make_float2(resx * 0.125f + bias[c],
                                resy * 0.125f + bias[c + 1]);
        *(float2*)(out + node * ODIM + c) = o2;
    }
}

// ---------------- launcher ---------------------------------------------------
// gemm_kernel stays at kernel-launch index 3 (the slot ncu captures).
extern "C" void kernel_launch(void* const* d_in, const int* in_sizes, int n_in,
                              void* d_out, int out_size)
{
    const float* x     = (const float*)d_in[0];
    const int*   ei    = (const int*)d_in[1];   // [2, E] — int32 (JAX x64 off)
    const float* W     = (const float*)d_in[3];
    const float* att_s = (const float*)d_in[4];
    const float* att_d = (const float*)d_in[5];
    const float* bias  = (const float*)d_in[6];
    float*       out   = (float*)d_out;

    int n = in_sizes[0] / IN_DIM;
    int e = in_sizes[1] / 2;
    int nb = (n + 255) / 256;
    const int smem_bytes = (4096 + 16384) * 4;   // 80 KB double-buffered

    cudaFuncSetAttribute(gemm_kernel,
                         cudaFuncAttributeMaxDynamicSharedMemorySize, smem_bytes);

    zero_kernel<<<nb, 256>>>(n);
    deg_kernel<<<(e + 255) / 256, 256>>>(ei, e, n);
    scan_a_kernel<<<nb, 256>>>(n);
    gemm_kernel<<<(n + 63) / 64, 256, smem_bytes>>>(x, W, att_s, att_d, n);
    scan_b_kernel<<<1, 256>>>(nb);
    scan_c_kernel<<<nb, 256>>>(n, e);
    fill_kernel<<<(e + 255) / 256, 256>>>(ei, e, n);
    agg_kernel<<<(n * 32 + 255) / 256, 256>>>(bias, out, n);
}

// round 8
// speedup vs baseline: 1.0976x; 1.0976x over previous
#include <cuda_runtime.h>
#include <cuda_fp16.h>

#define IN_DIM 128
#define HEADS 8
#define ODIM 32
#define HID 256            // HEADS*ODIM
#define NEG 0.2f
#define NMAX 50000
#define EMAX 800000

// GEMM tiling
#define BM 64
#define BN 256
#define BK 32
#define XS_STRIDE 36       // 64 rows x 32 k, padded (16B-aligned, conflict-free)
#define WS_STRIDE 260      // 32 k x 256 n, padded
#define XS_FLOATS (64 * XS_STRIDE)        // 2304
#define WS_FLOATS (32 * WS_STRIDE)        // 8320
#define SMEM_FLOATS (2 * XS_FLOATS + 2 * WS_FLOATS)   // 21248 = 83 KB
#define D_STRIDE 260

// ---------------- device scratch (static: no allocation allowed) -------------
__device__ __half g_hh[NMAX * HID];      // 25.6 MB (fp16 messages)
__device__ float  g_asrc[NMAX * HEADS];
__device__ float  g_adst[NMAX * HEADS];
__device__ int    g_deg[NMAX];
__device__ int    g_cur[NMAX];
__device__ int    g_off[NMAX + 1];
__device__ int    g_csrc[EMAX];
__device__ int    g_bsum[256];
__device__ int    g_bbase[256];

// ---------------- tf32 helpers -----------------------------------------------
__device__ __forceinline__ float tf32r(float v) {
    unsigned u;
    asm("cvt.rna.tf32.f32 %0, %1;" : "=r"(u) : "f"(v));
    return __uint_as_float(u);
}
__device__ __forceinline__ void mma_tf32(float4& d,
    unsigned a0, unsigned a1, unsigned a2, unsigned a3,
    unsigned b0, unsigned b1)
{
    asm volatile(
        "mma.sync.aligned.m16n8k8.row.col.f32.tf32.tf32.f32 "
        "{%0,%1,%2,%3}, {%4,%5,%6,%7}, {%8,%9}, {%0,%1,%2,%3};"
        : "+f"(d.x), "+f"(d.y), "+f"(d.z), "+f"(d.w)
        : "r"(a0), "r"(a1), "r"(a2), "r"(a3), "r"(b0), "r"(b1));
}

// ---------------- zero -------------------------------------------------------
__global__ void zero_kernel(int n) {
    int i = blockIdx.x * blockDim.x + threadIdx.x;
    if (i < n) { g_deg[i] = 0; g_cur[i] = 0; }
}

// ---------------- tf32 tensor-core GEMM + fused attention dots ---------------
// h = x @ W (N x 128 @ 128 x 256). 8 warps = 4(M) x 2(N); warp tile 16 x 128.
// Inputs cvt.rna'd to tf32 at the smem-staging step. Epilogue: D -> smem
// (aliased over k-buffers) -> fp16 h + per-head fp32 a_src/a_dst dots.
__global__ __launch_bounds__(256) void gemm_kernel(
    const float* __restrict__ x, const float* __restrict__ W,
    const float* __restrict__ att_s, const float* __restrict__ att_d, int n)
{
    extern __shared__ float smem[];
    float* xsb[2] = { smem,                    smem + XS_FLOATS };
    float* wsb[2] = { smem + 2 * XS_FLOATS,    smem + 2 * XS_FLOATS + WS_FLOATS };

    int tid  = threadIdx.x;
    int lane = tid & 31, wid = tid >> 5;
    int g    = lane >> 2, tig = lane & 3;        // mma group / thread-in-group
    int wm   = wid & 3,   wn  = wid >> 2;        // warp M (x16) / N (x128)
    int row0 = blockIdx.x * BM;

    float4 acc[16];
    #pragma unroll
    for (int t = 0; t < 16; t++) acc[t] = make_float4(0.f, 0.f, 0.f, 0.f);

    // staging registers
    float4 xr[2];
    float4 wr[8];

    auto ldg_tile = [&](int kt) {
        #pragma unroll
        for (int t = 0; t < 2; t++) {
            int q = tid + t * 256;
            int r = q >> 3, k4 = q & 7;
            int grow = row0 + r;
            xr[t] = (grow < n)
                ? ((const float4*)x)[(size_t)grow * (IN_DIM / 4) + kt * 8 + k4]
                : make_float4(0.f, 0.f, 0.f, 0.f);
        }
        #pragma unroll
        for (int t = 0; t < 8; t++) {
            int q = tid + t * 256;
            int r = q >> 6, c4 = q & 63;
            wr[t] = ((const float4*)W)[(size_t)(kt * 32 + r) * 64 + c4];
        }
    };
    auto sts_tile = [&](int b) {
        float* xs = xsb[b];
        float* ws = wsb[b];
        #pragma unroll
        for (int t = 0; t < 2; t++) {
            int q = tid + t * 256;
            int r = q >> 3, k4 = q & 7;
            float4 v = xr[t];
            v.x = tf32r(v.x); v.y = tf32r(v.y); v.z = tf32r(v.z); v.w = tf32r(v.w);
            *(float4*)(xs + r * XS_STRIDE + k4 * 4) = v;
        }
        #pragma unroll
        for (int t = 0; t < 8; t++) {
            int q = tid + t * 256;
            int r = q >> 6, c4 = q & 63;
            float4 v = wr[t];
            v.x = tf32r(v.x); v.y = tf32r(v.y); v.z = tf32r(v.z); v.w = tf32r(v.w);
            *(float4*)(ws + r * WS_STRIDE + c4 * 4) = v;
        }
    };

    ldg_tile(0);
    sts_tile(0);
    __syncthreads();

    #pragma unroll
    for (int kt = 0; kt < 4; kt++) {
        if (kt < 3) ldg_tile(kt + 1);

        const float* xs = xsb[kt & 1];
        const float* ws = wsb[kt & 1];
        #pragma unroll
        for (int ks = 0; ks < 4; ks++) {
            int kk = ks * 8;
            const float* xa = xs + (wm * 16) * XS_STRIDE + kk;
            unsigned a0 = __float_as_uint(xa[g * XS_STRIDE + tig]);
            unsigned a1 = __float_as_uint(xa[(g + 8) * XS_STRIDE + tig]);
            unsigned a2 = __float_as_uint(xa[g * XS_STRIDE + tig + 4]);
            unsigned a3 = __float_as_uint(xa[(g + 8) * XS_STRIDE + tig + 4]);
            const float* wb = ws + kk * WS_STRIDE + wn * 128 + g;
            #pragma unroll
            for (int nt = 0; nt < 16; nt++) {
                unsigned b0 = __float_as_uint(wb[tig * WS_STRIDE + nt * 8]);
                unsigned b1 = __float_as_uint(wb[(tig + 4) * WS_STRIDE + nt * 8]);
                mma_tf32(acc[nt], a0, a1, a2, a3, b0, b1);
            }
        }
        __syncthreads();
        if (kt < 3) {
            sts_tile((kt + 1) & 1);
            __syncthreads();
        }
    }

    // ---- epilogue: D -> smem (alias over buffers; all compute is done) ------
    float* Dsm = smem;                 // 64 x D_STRIDE = 66.6 KB <= 83 KB
    {
        int rbase = wm * 16;
        int cbase = wn * 128 + tig * 2;
        #pragma unroll
        for (int nt = 0; nt < 16; nt++) {
            int c = cbase + nt * 8;
            *(float2*)(Dsm + (rbase + g) * D_STRIDE + c)     = make_float2(acc[nt].x, acc[nt].y);
            *(float2*)(Dsm + (rbase + g + 8) * D_STRIDE + c) = make_float2(acc[nt].z, acc[nt].w);
        }
    }
    __syncthreads();

    // thread: row = tid>>2 (64 rows), part = tid&3 -> cols part*64..+63 = heads 2p,2p+1
    {
        int row  = tid >> 2, part = tid & 3;
        int grow = row0 + row;
        if (grow < n) {
            int c0 = part * 64;
            float d[64];
            #pragma unroll
            for (int i = 0; i < 16; i++)
                *(float4*)(d + i * 4) = *(const float4*)(Dsm + row * D_STRIDE + c0 + i * 4);

            // fp16 h store
            __half2 hv[4];
            #pragma unroll
            for (int i = 0; i < 8; i++) {
                #pragma unroll
                for (int p = 0; p < 4; p++)
                    hv[p] = __floats2half2_rn(d[i * 8 + 2 * p], d[i * 8 + 2 * p + 1]);
                *(uint4*)(g_hh + (size_t)grow * HID + c0 + i * 8) = *(uint4*)hv;
            }

            // per-head attention dots (cols c0..c0+31 = head 2p, +32.. = head 2p+1)
            float s0 = 0.f, s1 = 0.f, t0 = 0.f, t1 = 0.f;
            #pragma unroll
            for (int j = 0; j < 32; j++) {
                s0 += d[j]      * att_s[c0 + j];
                t0 += d[j]      * att_d[c0 + j];
                s1 += d[j + 32] * att_s[c0 + 32 + j];
                t1 += d[j + 32] * att_d[c0 + 32 + j];
            }
            int h0 = 2 * part;
            g_asrc[grow * HEADS + h0]     = s0;
            g_asrc[grow * HEADS + h0 + 1] = s1;
            g_adst[grow * HEADS + h0]     = t0;
            g_adst[grow * HEADS + h0 + 1] = t1;
        }
    }
}

// ---------------- degree histogram (edge_index is int32: JAX demotes int64) --
__global__ void deg_kernel(const int* __restrict__ ei, int e, int n) {
    int i = blockIdx.x * blockDim.x + threadIdx.x;
    if (i < e) {
        int d = ei[e + i];   // dst row of edge_index [2, E]
        if ((unsigned)d < (unsigned)n) atomicAdd(&g_deg[d], 1);
    }
}

// ---------------- 3-kernel exclusive scan ------------------------------------
__device__ __forceinline__ int block_scan_incl(int v, int tid) {
    __shared__ int wsum[8];
    int lane = tid & 31, w = tid >> 5;
    int x = v;
    #pragma unroll
    for (int o = 1; o < 32; o <<= 1) {
        int y = __shfl_up_sync(0xffffffffu, x, o);
        if (lane >= o) x += y;
    }
    if (lane == 31) wsum[w] = x;
    __syncthreads();
    if (tid < 8) {
        int y = wsum[tid];
        #pragma unroll
        for (int o = 1; o < 8; o <<= 1) {
            int z = __shfl_up_sync(0xffu, y, o);
            if (tid >= o) y += z;
        }
        wsum[tid] = y;
    }
    __syncthreads();
    int base = (w > 0) ? wsum[w - 1] : 0;
    return x + base;
}

__global__ void scan_a_kernel(int n) {
    int i = blockIdx.x * 256 + threadIdx.x;
    int v = (i < n) ? g_deg[i] : 0;
    int incl = block_scan_incl(v, threadIdx.x);
    if (i < n) g_off[i] = incl - v;
    if (threadIdx.x == 255) g_bsum[blockIdx.x] = incl;
}

__global__ void scan_b_kernel(int nb) {
    int t = threadIdx.x;
    int v = (t < nb) ? g_bsum[t] : 0;
    int incl = block_scan_incl(v, t);
    g_bbase[t] = incl - v;
}

__global__ void scan_c_kernel(int n, int e) {
    int i = blockIdx.x * 256 + threadIdx.x;
    if (i < n) g_off[i] += g_bbase[blockIdx.x];
    if (i == 0) g_off[n] = e;
}

// ---------------- CSR fill ---------------------------------------------------
__global__ void fill_kernel(const int* __restrict__ ei, int e, int n) {
    int i = blockIdx.x * blockDim.x + threadIdx.x;
    if (i < e) {
        int d = ei[e + i];
        int s = ei[i];
        if ((unsigned)d < (unsigned)n) {
            int p = atomicAdd(&g_cur[d], 1);
            g_csrc[g_off[d] + p] = s;
        }
    }
}

// ---------------- single-pass softmax + aggregate ----------------------------
// No max-shift: logits are O(10), exp() safe in fp32, softmax shift-invariant.
__global__ __launch_bounds__(256) void agg_kernel(
    const float* __restrict__ bias, float* __restrict__ out, int n)
{
    int warp = (blockIdx.x * blockDim.x + threadIdx.x) >> 5;
    int lane = threadIdx.x & 31;
    if (warp >= n) return;
    int node = warp;
    int beg = g_off[node], end = g_off[node + 1];

    float adl = (lane < HEADS) ? g_adst[node * HEADS + lane] : 0.f;

    float accx[4], accy[4];
    #pragma unroll
    for (int k = 0; k < 4; k++) { accx[k] = 0.f; accy[k] = 0.f; }
    float s_l = 0.f;               // lane<8: softmax denom for head=lane
    int hsel = lane >> 4;          // 0: even heads, 1: odd heads

    for (int i = beg; i <= end; i++) {
        int src = (i < end) ? g_csrc[i] : node;   // final iter = self loop
        float ex = 0.f;
        if (lane < 8) {
            float ev = g_asrc[src * HEADS + lane] + adl;
            ev = ev > 0.f ? ev : NEG * ev;
            ex = __expf(ev);
            s_l += ex;
        }
        const __half2* hp = (const __half2*)(g_hh + (size_t)src * HID);
        #pragma unroll
        for (int k = 0; k < 4; k++) {
            float exk = __shfl_sync(0xffffffffu, ex, 2 * k + hsel);
            float2 hv = __half22float2(hp[k * 32 + lane]);
            accx[k] = fmaf(exk, hv.x, accx[k]);
            accy[k] = fmaf(exk, hv.y, accy[k]);
        }
    }

    float inv_l = (lane < HEADS) ? __frcp_rn(s_l) : 0.f;
    float resx = 0.f, resy = 0.f;
    #pragma unroll
    for (int k = 0; k < 4; k++) {
        float invk = __shfl_sync(0xffffffffu, inv_l, 2 * k + hsel);
        resx = fmaf(accx[k], invk, resx);
        resy = fmaf(accy[k], invk, resy);
    }
    resx += __shfl_xor_sync(0xffffffffu, resx, 16);
    resy += __shfl_xor_sync(0xffffffffu, resy, 16);
    if (lane < 16) {
        int c = 2 * lane;
        float2 o2 = make_float2(resx * 0.125f + bias[c],
                                resy * 0.125f + bias[c + 1]);
        *(float2*)(out + node * ODIM + c) = o2;
    }
}

// ---------------- launcher ---------------------------------------------------
// gemm_kernel stays at kernel-launch index 3 (the slot ncu captures).
extern "C" void kernel_launch(void* const* d_in, const int* in_sizes, int n_in,
                              void* d_out, int out_size)
{
    const float* x     = (const float*)d_in[0];
    const int*   ei    = (const int*)d_in[1];   // [2, E] — int32 (JAX x64 off)
    const float* W     = (const float*)d_in[3];
    const float* att_s = (const float*)d_in[4];
    const float* att_d = (const float*)d_in[5];
    const float* bias  = (const float*)d_in[6];
    float*       out   = (float*)d_out;

    int n = in_sizes[0] / IN_DIM;
    int e = in_sizes[1] / 2;
    int nb = (n + 255) / 256;
    const int smem_bytes = SMEM_FLOATS * 4;   // 83 KB

    cudaFuncSetAttribute(gemm_kernel,
                         cudaFuncAttributeMaxDynamicSharedMemorySize, smem_bytes);

    zero_kernel<<<nb, 256>>>(n);
    deg_kernel<<<(e + 255) / 256, 256>>>(ei, e, n);
    scan_a_kernel<<<nb, 256>>>(n);
    gemm_kernel<<<(n + BM - 1) / BM, 256, smem_bytes>>>(x, W, att_s, att_d, n);
    scan_b_kernel<<<1, 256>>>(nb);
    scan_c_kernel<<<nb, 256>>>(n, e);
    fill_kernel<<<(e + 255) / 256, 256>>>(ei, e, n);
    agg_kernel<<<(n * 32 + 255) / 256, 256>>>(bias, out, n);
}

// round 10
// speedup vs baseline: 1.1680x; 1.0641x over previous
#include <cuda_runtime.h>
#include <cuda_fp16.h>

#define IN_DIM 128
#define HEADS 8
#define ODIM 32
#define HID 256            // HEADS*ODIM
#define NEG 0.2f
#define NMAX 50000
#define EMAX 800000

// GEMM tiling: block 64x256, k-tile 32, warps 4(M) x 2(N), warp tile 16x128 (R8 layout)
#define BM 64
#define XS_STRIDE 36       // (4g+tig) banks -> conflict-free A frag loads
#define WS_STRIDE 264      // (g+8tig) banks -> conflict-free B frag loads
#define XS_FLOATS (64 * XS_STRIDE)                 // 2304
#define WS_FLOATS (32 * WS_STRIDE)                 // 8448
#define BUF_FLOATS (XS_FLOATS + WS_FLOATS)         // 10752
#define SMEM_FLOATS (2 * BUF_FLOATS)               // 21504 -> 84 KB (2 CTAs/SM)
#define D_STRIDE 260       // row-major epilogue D (R8-verified)

// ---------------- device scratch (static: no allocation allowed) -------------
__device__ __half g_hh[NMAX * HID];      // 25.6 MB (fp16 messages)
__device__ float  g_asrc[NMAX * HEADS];
__device__ float  g_adst[NMAX * HEADS];
__device__ int    g_deg[NMAX];
__device__ int    g_cur[NMAX];
__device__ int    g_off[NMAX + 1];
__device__ int    g_csrc[EMAX];
__device__ int    g_bsum[256];
__device__ int    g_bbase[256];

// ---------------- helpers ----------------------------------------------------
__device__ __forceinline__ void cp16(void* dst, const void* src, bool pred) {
    unsigned d = (unsigned)__cvta_generic_to_shared(dst);
    int sz = pred ? 16 : 0;
    asm volatile("cp.async.cg.shared.global [%0], [%1], 16, %2;"
                 :: "r"(d), "l"(src), "r"(sz) : "memory");
}
__device__ __forceinline__ unsigned tf32u(float v) {
    unsigned u;
    asm("cvt.rna.tf32.f32 %0, %1;" : "=r"(u) : "f"(v));
    return u;
}
__device__ __forceinline__ void mma_tf32(float4& d,
    unsigned a0, unsigned a1, unsigned a2, unsigned a3,
    unsigned b0, unsigned b1)
{
    asm volatile(
        "mma.sync.aligned.m16n8k8.row.col.f32.tf32.tf32.f32 "
        "{%0,%1,%2,%3}, {%4,%5,%6,%7}, {%8,%9}, {%0,%1,%2,%3};"
        : "+f"(d.x), "+f"(d.y), "+f"(d.z), "+f"(d.w)
        : "r"(a0), "r"(a1), "r"(a2), "r"(a3), "r"(b0), "r"(b1));
}

// ---------------- zero -------------------------------------------------------
__global__ void zero_kernel(int n) {
    int i = blockIdx.x * blockDim.x + threadIdx.x;
    if (i < n) { g_deg[i] = 0; g_cur[i] = 0; }
}

// ---------------- tf32 tensor-core GEMM + fused attention dots ---------------
// R8-verified warp layout + epilogue; cp.async loader; 2 CTAs/SM.
__global__ void __launch_bounds__(256, 2) gemm_kernel(
    const float* __restrict__ x, const float* __restrict__ W,
    const float* __restrict__ att_s, const float* __restrict__ att_d, int n)
{
    extern __shared__ float smem[];
    float* xsb[2] = { smem,             smem + BUF_FLOATS };
    float* wsb[2] = { smem + XS_FLOATS, smem + BUF_FLOATS + XS_FLOATS };

    int tid  = threadIdx.x;
    int lane = tid & 31, wid = tid >> 5;
    int g    = lane >> 2, tig = lane & 3;
    int wm   = wid & 3,   wn  = wid >> 2;      // 4(M) x 2(N)  [R8]
    int row0 = blockIdx.x * BM;

    auto issue = [&](int kt, int b) {
        float* xs = xsb[b];
        float* ws = wsb[b];
        #pragma unroll
        for (int t = 0; t < 2; t++) {
            int q = tid + t * 256;
            int r = q >> 3, k4 = q & 7;
            int grow = row0 + r;
            cp16(xs + r * XS_STRIDE + k4 * 4,
                 x + (size_t)grow * IN_DIM + kt * 32 + k4 * 4, grow < n);
        }
        #pragma unroll
        for (int t = 0; t < 8; t++) {
            int q = tid + t * 256;
            int r = q >> 6, c4 = q & 63;
            cp16(ws + r * WS_STRIDE + c4 * 4,
                 W + (size_t)(kt * 32 + r) * 256 + c4 * 4, true);
        }
        asm volatile("cp.async.commit_group;" ::: "memory");
    };

    float4 acc[16];
    #pragma unroll
    for (int t = 0; t < 16; t++) acc[t] = make_float4(0.f, 0.f, 0.f, 0.f);

    issue(0, 0);

    #pragma unroll
    for (int kt = 0; kt < 4; kt++) {
        if (kt < 3) issue(kt + 1, (kt + 1) & 1);
        if (kt < 3) asm volatile("cp.async.wait_group 1;" ::: "memory");
        else        asm volatile("cp.async.wait_group 0;" ::: "memory");
        __syncthreads();

        const float* xs = xsb[kt & 1];
        const float* ws = wsb[kt & 1];
        #pragma unroll
        for (int ks = 0; ks < 4; ks++) {
            int kk = ks * 8;
            const float* xa = xs + (wm * 16) * XS_STRIDE + kk;
            unsigned a0 = tf32u(xa[g * XS_STRIDE + tig]);
            unsigned a1 = tf32u(xa[(g + 8) * XS_STRIDE + tig]);
            unsigned a2 = tf32u(xa[g * XS_STRIDE + tig + 4]);
            unsigned a3 = tf32u(xa[(g + 8) * XS_STRIDE + tig + 4]);
            const float* wb = ws + kk * WS_STRIDE + wn * 128 + g;
            #pragma unroll
            for (int nt = 0; nt < 16; nt++) {
                unsigned b0 = tf32u(wb[tig * WS_STRIDE + nt * 8]);
                unsigned b1 = tf32u(wb[(tig + 4) * WS_STRIDE + nt * 8]);
                mma_tf32(acc[nt], a0, a1, a2, a3, b0, b1);
            }
        }
        __syncthreads();
    }

    // ---- epilogue: D -> smem row-major (R8-verified), then h + dots ---------
    float* Dsm = smem;                 // 64 x D_STRIDE = 66.6 KB <= 84 KB
    {
        int rbase = wm * 16;
        int cbase = wn * 128 + tig * 2;
        #pragma unroll
        for (int nt = 0; nt < 16; nt++) {
            int c = cbase + nt * 8;
            *(float2*)(Dsm + (rbase + g) * D_STRIDE + c)     = make_float2(acc[nt].x, acc[nt].y);
            *(float2*)(Dsm + (rbase + g + 8) * D_STRIDE + c) = make_float2(acc[nt].z, acc[nt].w);
        }
    }
    __syncthreads();

    // thread: row = tid>>2 (64 rows), part = tid&3 -> cols part*64..+63 = heads 2p,2p+1
    {
        int row  = tid >> 2, part = tid & 3;
        int grow = row0 + row;
        if (grow < n) {
            int c0 = part * 64;
            float d[64];
            #pragma unroll
            for (int i = 0; i < 16; i++)
                *(float4*)(d + i * 4) = *(const float4*)(Dsm + row * D_STRIDE + c0 + i * 4);

            // fp16 h store
            __half2 hv[4];
            #pragma unroll
            for (int i = 0; i < 8; i++) {
                #pragma unroll
                for (int p = 0; p < 4; p++)
                    hv[p] = __floats2half2_rn(d[i * 8 + 2 * p], d[i * 8 + 2 * p + 1]);
                *(uint4*)(g_hh + (size_t)grow * HID + c0 + i * 8) = *(uint4*)hv;
            }

            // per-head attention dots (cols c0..c0+31 = head 2p, +32.. = head 2p+1)
            float s0 = 0.f, s1 = 0.f, t0 = 0.f, t1 = 0.f;
            #pragma unroll
            for (int j = 0; j < 32; j++) {
                s0 += d[j]      * att_s[c0 + j];
                t0 += d[j]      * att_d[c0 + j];
                s1 += d[j + 32] * att_s[c0 + 32 + j];
                t1 += d[j + 32] * att_d[c0 + 32 + j];
            }
            int h0 = 2 * part;
            g_asrc[grow * HEADS + h0]     = s0;
            g_asrc[grow * HEADS + h0 + 1] = s1;
            g_adst[grow * HEADS + h0]     = t0;
            g_adst[grow * HEADS + h0 + 1] = t1;
        }
    }
}

// ---------------- degree histogram (edge_index is int32: JAX demotes int64) --
__global__ void deg_kernel(const int* __restrict__ ei, int e, int n) {
    int i = blockIdx.x * blockDim.x + threadIdx.x;
    if (i < e) {
        int d = ei[e + i];   // dst row of edge_index [2, E]
        if ((unsigned)d < (unsigned)n) atomicAdd(&g_deg[d], 1);
    }
}

// ---------------- 3-kernel exclusive scan ------------------------------------
__device__ __forceinline__ int block_scan_incl(int v, int tid) {
    __shared__ int wsum[8];
    int lane = tid & 31, w = tid >> 5;
    int x = v;
    #pragma unroll
    for (int o = 1; o < 32; o <<= 1) {
        int y = __shfl_up_sync(0xffffffffu, x, o);
        if (lane >= o) x += y;
    }
    if (lane == 31) wsum[w] = x;
    __syncthreads();
    if (tid < 8) {
        int y = wsum[tid];
        #pragma unroll
        for (int o = 1; o < 8; o <<= 1) {
            int z = __shfl_up_sync(0xffu, y, o);
            if (tid >= o) y += z;
        }
        wsum[tid] = y;
    }
    __syncthreads();
    int base = (w > 0) ? wsum[w - 1] : 0;
    return x + base;
}

__global__ void scan_a_kernel(int n) {
    int i = blockIdx.x * 256 + threadIdx.x;
    int v = (i < n) ? g_deg[i] : 0;
    int incl = block_scan_incl(v, threadIdx.x);
    if (i < n) g_off[i] = incl - v;
    if (threadIdx.x == 255) g_bsum[blockIdx.x] = incl;
}

__global__ void scan_b_kernel(int nb) {
    int t = threadIdx.x;
    int v = (t < nb) ? g_bsum[t] : 0;
    int incl = block_scan_incl(v, t);
    g_bbase[t] = incl - v;
}

__global__ void scan_c_kernel(int n, int e) {
    int i = blockIdx.x * 256 + threadIdx.x;
    if (i < n) g_off[i] += g_bbase[blockIdx.x];
    if (i == 0) g_off[n] = e;
}

// ---------------- CSR fill ---------------------------------------------------
__global__ void fill_kernel(const int* __restrict__ ei, int e, int n) {
    int i = blockIdx.x * blockDim.x + threadIdx.x;
    if (i < e) {
        int d = ei[e + i];
        int s = ei[i];
        if ((unsigned)d < (unsigned)n) {
            int p = atomicAdd(&g_cur[d], 1);
            g_csrc[g_off[d] + p] = s;
        }
    }
}

// ---------------- single-pass softmax + aggregate ----------------------------
__global__ __launch_bounds__(256) void agg_kernel(
    const float* __restrict__ bias, float* __restrict__ out, int n)
{
    int warp = (blockIdx.x * blockDim.x + threadIdx.x) >> 5;
    int lane = threadIdx.x & 31;
    if (warp >= n) return;
    int node = warp;
    int beg = g_off[node], end = g_off[node + 1];

    float adl = (lane < HEADS) ? g_adst[node * HEADS + lane] : 0.f;

    float accx[4], accy[4];
    #pragma unroll
    for (int k = 0; k < 4; k++) { accx[k] = 0.f; accy[k] = 0.f; }
    float s_l = 0.f;               // lane<8: softmax denom for head=lane
    int hsel = lane >> 4;          // 0: even heads, 1: odd heads

    for (int i = beg; i <= end; i++) {
        int src = (i < end) ? g_csrc[i] : node;   // final iter = self loop
        float ex = 0.f;
        if (lane < 8) {
            float ev = g_asrc[src * HEADS + lane] + adl;
            ev = ev > 0.f ? ev : NEG * ev;
            ex = __expf(ev);
            s_l += ex;
        }
        const __half2* hp = (const __half2*)(g_hh + (size_t)src * HID);
        #pragma unroll
        for (int k = 0; k < 4; k++) {
            float exk = __shfl_sync(0xffffffffu, ex, 2 * k + hsel);
            float2 hv = __half22float2(hp[k * 32 + lane]);
            accx[k] = fmaf(exk, hv.x, accx[k]);
            accy[k] = fmaf(exk, hv.y, accy[k]);
        }
    }

    float inv_l = (lane < HEADS) ? __frcp_rn(s_l) : 0.f;
    float resx = 0.f, resy = 0.f;
    #pragma unroll
    for (int k = 0; k < 4; k++) {
        float invk = __shfl_sync(0xffffffffu, inv_l, 2 * k + hsel);
        resx = fmaf(accx[k], invk, resx);
        resy = fmaf(accy[k], invk, resy);
    }
    resx += __shfl_xor_sync(0xffffffffu, resx, 16);
    resy += __shfl_xor_sync(0xffffffffu, resy, 16);
    if (lane < 16) {
        int c = 2 * lane;
        float2 o2 = make_float2(resx * 0.125f + bias[c],
                                resy * 0.125f + bias[c + 1]);
        *(float2*)(out + node * ODIM + c) = o2;
    }
}

// ---------------- launcher ---------------------------------------------------
// gemm_kernel stays at kernel-launch index 3 (the slot ncu captures).
extern "C" void kernel_launch(void* const* d_in, const int* in_sizes, int n_in,
                              void* d_out, int out_size)
{
    const float* x     = (const float*)d_in[0];
    const int*   ei    = (const int*)d_in[1];   // [2, E] — int32 (JAX x64 off)
    const float* W     = (const float*)d_in[3];
    const float* att_s = (const float*)d_in[4];
    const float* att_d = (const float*)d_in[5];
    const float* bias  = (const float*)d_in[6];
    float*       out   = (float*)d_out;

    int n = in_sizes[0] / IN_DIM;
    int e = in_sizes[1] / 2;
    int nb = (n + 255) / 256;
    const int smem_bytes = SMEM_FLOATS * 4;   // 86016 B

    cudaFuncSetAttribute(gemm_kernel,
                         cudaFuncAttributeMaxDynamicSharedMemorySize, smem_bytes);

    zero_kernel<<<nb, 256>>>(n);
    deg_kernel<<<(e + 255) / 256, 256>>>(ei, e, n);
    scan_a_kernel<<<nb, 256>>>(n);
    gemm_kernel<<<(n + BM - 1) / BM, 256, smem_bytes>>>(x, W, att_s, att_d, n);
    scan_b_kernel<<<1, 256>>>(nb);
    scan_c_kernel<<<nb, 256>>>(n, e);
    fill_kernel<<<(e + 255) / 256, 256>>>(ei, e, n);
    agg_kernel<<<(n * 32 + 255) / 256, 256>>>(bias, out, n);
}

// round 11
// speedup vs baseline: 1.2309x; 1.0539x over previous
#include <cuda_runtime.h>
#include <cuda_fp16.h>

#define IN_DIM 128
#define HEADS 8
#define ODIM 32
#define HID 256            // HEADS*ODIM
#define NEG 0.2f
#define NMAX 50000
#define EMAX 800000
#define WELEM (IN_DIM * HID)   // 32768

// GEMM tiling: block 64x256, k-tile 32, warps 4(M) x 2(N), warp tile 16x128
#define BM 64
#define XS_STRIDE 36
#define WS_STRIDE 264
#define XS_FLOATS (64 * XS_STRIDE)                 // 2304
#define WS_FLOATS (32 * WS_STRIDE)                 // 8448
#define BUF_FLOATS (XS_FLOATS + WS_FLOATS)         // 10752
#define SMEM_FLOATS (2 * BUF_FLOATS)               // 84 KB -> 2 CTAs/SM
#define D_STRIDE 260

// ---------------- device scratch (static: no allocation allowed) -------------
__device__ __half g_hh[NMAX * HID];      // 25.6 MB (fp16 messages)
__device__ float  g_asrc[NMAX * HEADS];
__device__ float  g_adst[NMAX * HEADS];
__device__ float  g_wt[WELEM];           // W pre-rounded to tf32 bit pattern
__device__ int    g_deg[NMAX];
__device__ int    g_rank[EMAX];          // edge rank within its dst bucket
__device__ int    g_off[NMAX + 1];
__device__ int    g_csrc[EMAX];
__device__ int    g_bsum[256];
__device__ int    g_bbase[256];

// ---------------- helpers ----------------------------------------------------
__device__ __forceinline__ void cp16(void* dst, const void* src, bool pred) {
    unsigned d = (unsigned)__cvta_generic_to_shared(dst);
    int sz = pred ? 16 : 0;
    asm volatile("cp.async.cg.shared.global [%0], [%1], 16, %2;"
                 :: "r"(d), "l"(src), "r"(sz) : "memory");
}
__device__ __forceinline__ unsigned tf32u(float v) {
    unsigned u;
    asm("cvt.rna.tf32.f32 %0, %1;" : "=r"(u) : "f"(v));
    return u;
}
__device__ __forceinline__ void mma_tf32(float4& d,
    unsigned a0, unsigned a1, unsigned a2, unsigned a3,
    unsigned b0, unsigned b1)
{
    asm volatile(
        "mma.sync.aligned.m16n8k8.row.col.f32.tf32.tf32.f32 "
        "{%0,%1,%2,%3}, {%4,%5,%6,%7}, {%8,%9}, {%0,%1,%2,%3};"
        : "+f"(d.x), "+f"(d.y), "+f"(d.z), "+f"(d.w)
        : "r"(a0), "r"(a1), "r"(a2), "r"(a3), "r"(b0), "r"(b1));
}

// ---------------- zero + W->tf32 pre-convert ---------------------------------
__global__ void zero_kernel(const float* __restrict__ W, int n) {
    int i = blockIdx.x * blockDim.x + threadIdx.x;
    if (i < n) g_deg[i] = 0;
    if (i < WELEM) g_wt[i] = __uint_as_float(tf32u(W[i]));
}

// ---------------- tf32 tensor-core GEMM + fused attention dots ---------------
__global__ void __launch_bounds__(256, 2) gemm_kernel(
    const float* __restrict__ x,
    const float* __restrict__ att_s, const float* __restrict__ att_d, int n)
{
    extern __shared__ float smem[];
    float* xsb[2] = { smem,             smem + BUF_FLOATS };
    float* wsb[2] = { smem + XS_FLOATS, smem + BUF_FLOATS + XS_FLOATS };

    int tid  = threadIdx.x;
    int lane = tid & 31, wid = tid >> 5;
    int g    = lane >> 2, tig = lane & 3;
    int wm   = wid & 3,   wn  = wid >> 2;      // 4(M) x 2(N)
    int row0 = blockIdx.x * BM;

    auto issue = [&](int kt, int b) {
        float* xs = xsb[b];
        float* ws = wsb[b];
        #pragma unroll
        for (int t = 0; t < 2; t++) {
            int q = tid + t * 256;
            int r = q >> 3, k4 = q & 7;
            int grow = row0 + r;
            cp16(xs + r * XS_STRIDE + k4 * 4,
                 x + (size_t)grow * IN_DIM + kt * 32 + k4 * 4, grow < n);
        }
        #pragma unroll
        for (int t = 0; t < 8; t++) {
            int q = tid + t * 256;
            int r = q >> 6, c4 = q & 63;
            cp16(ws + r * WS_STRIDE + c4 * 4,
                 g_wt + (size_t)(kt * 32 + r) * 256 + c4 * 4, true);
        }
        asm volatile("cp.async.commit_group;" ::: "memory");
    };

    float4 acc[16];
    #pragma unroll
    for (int t = 0; t < 16; t++) acc[t] = make_float4(0.f, 0.f, 0.f, 0.f);

    issue(0, 0);

    #pragma unroll
    for (int kt = 0; kt < 4; kt++) {
        if (kt < 3) issue(kt + 1, (kt + 1) & 1);
        if (kt < 3) asm volatile("cp.async.wait_group 1;" ::: "memory");
        else        asm volatile("cp.async.wait_group 0;" ::: "memory");
        __syncthreads();

        const float* xs = xsb[kt & 1];
        const float* ws = wsb[kt & 1];
        #pragma unroll
        for (int ks = 0; ks < 4; ks++) {
            int kk = ks * 8;
            const float* xa = xs + (wm * 16) * XS_STRIDE + kk;
            unsigned a0 = tf32u(xa[g * XS_STRIDE + tig]);
            unsigned a1 = tf32u(xa[(g + 8) * XS_STRIDE + tig]);
            unsigned a2 = tf32u(xa[g * XS_STRIDE + tig + 4]);
            unsigned a3 = tf32u(xa[(g + 8) * XS_STRIDE + tig + 4]);
            const float* wb = ws + kk * WS_STRIDE + wn * 128 + g;
            // B is pre-rounded to tf32 bits: LDS feeds HMMA directly.
            // Chunks of 4 nt: batch 8 independent LDS, then 4 MMAs.
            #pragma unroll
            for (int nc = 0; nc < 4; nc++) {
                unsigned bq[8];
                #pragma unroll
                for (int j = 0; j < 4; j++) {
                    int nt = nc * 4 + j;
                    bq[2 * j]     = __float_as_uint(wb[tig * WS_STRIDE + nt * 8]);
                    bq[2 * j + 1] = __float_as_uint(wb[(tig + 4) * WS_STRIDE + nt * 8]);
                }
                #pragma unroll
                for (int j = 0; j < 4; j++)
                    mma_tf32(acc[nc * 4 + j], a0, a1, a2, a3, bq[2 * j], bq[2 * j + 1]);
            }
        }
        __syncthreads();
    }

    // ---- epilogue: D -> smem row-major (R8-verified), then h + dots ---------
    float* Dsm = smem;                 // 64 x D_STRIDE = 66.6 KB <= 84 KB
    {
        int rbase = wm * 16;
        int cbase = wn * 128 + tig * 2;
        #pragma unroll
        for (int nt = 0; nt < 16; nt++) {
            int c = cbase + nt * 8;
            *(float2*)(Dsm + (rbase + g) * D_STRIDE + c)     = make_float2(acc[nt].x, acc[nt].y);
            *(float2*)(Dsm + (rbase + g + 8) * D_STRIDE + c) = make_float2(acc[nt].z, acc[nt].w);
        }
    }
    __syncthreads();

    {
        int row  = tid >> 2, part = tid & 3;
        int grow = row0 + row;
        if (grow < n) {
            int c0 = part * 64;
            float d[64];
            #pragma unroll
            for (int i = 0; i < 16; i++)
                *(float4*)(d + i * 4) = *(const float4*)(Dsm + row * D_STRIDE + c0 + i * 4);

            __half2 hv[4];
            #pragma unroll
            for (int i = 0; i < 8; i++) {
                #pragma unroll
                for (int p = 0; p < 4; p++)
                    hv[p] = __floats2half2_rn(d[i * 8 + 2 * p], d[i * 8 + 2 * p + 1]);
                *(uint4*)(g_hh + (size_t)grow * HID + c0 + i * 8) = *(uint4*)hv;
            }

            float s0 = 0.f, s1 = 0.f, t0 = 0.f, t1 = 0.f;
            #pragma unroll
            for (int j = 0; j < 32; j++) {
                s0 += d[j]      * att_s[c0 + j];
                t0 += d[j]      * att_d[c0 + j];
                s1 += d[j + 32] * att_s[c0 + 32 + j];
                t1 += d[j + 32] * att_d[c0 + 32 + j];
            }
            int h0 = 2 * part;
            g_asrc[grow * HEADS + h0]     = s0;
            g_asrc[grow * HEADS + h0 + 1] = s1;
            g_adst[grow * HEADS + h0]     = t0;
            g_adst[grow * HEADS + h0 + 1] = t1;
        }
    }
}

// ---------------- degree histogram + per-edge rank ---------------------------
__global__ void deg_kernel(const int* __restrict__ ei, int e, int n) {
    int i = blockIdx.x * blockDim.x + threadIdx.x;
    if (i < e) {
        int d = ei[e + i];   // dst row of edge_index [2, E]
        int r = 0;
        if ((unsigned)d < (unsigned)n) r = atomicAdd(&g_deg[d], 1);
        g_rank[i] = r;
    }
}

// ---------------- 3-kernel exclusive scan ------------------------------------
__device__ __forceinline__ int block_scan_incl(int v, int tid) {
    __shared__ int wsum[8];
    int lane = tid & 31, w = tid >> 5;
    int x = v;
    #pragma unroll
    for (int o = 1; o < 32; o <<= 1) {
        int y = __shfl_up_sync(0xffffffffu, x, o);
        if (lane >= o) x += y;
    }
    if (lane == 31) wsum[w] = x;
    __syncthreads();
    if (tid < 8) {
        int y = wsum[tid];
        #pragma unroll
        for (int o = 1; o < 8; o <<= 1) {
            int z = __shfl_up_sync(0xffu, y, o);
            if (tid >= o) y += z;
        }
        wsum[tid] = y;
    }
    __syncthreads();
    int base = (w > 0) ? wsum[w - 1] : 0;
    return x + base;
}

__global__ void scan_a_kernel(int n) {
    int i = blockIdx.x * 256 + threadIdx.x;
    int v = (i < n) ? g_deg[i] : 0;
    int incl = block_scan_incl(v, threadIdx.x);
    if (i < n) g_off[i] = incl - v;
    if (threadIdx.x == 255) g_bsum[blockIdx.x] = incl;
}

__global__ void scan_b_kernel(int nb) {
    int t = threadIdx.x;
    int v = (t < nb) ? g_bsum[t] : 0;
    int incl = block_scan_incl(v, t);
    g_bbase[t] = incl - v;
}

__global__ void scan_c_kernel(int n, int e) {
    int i = blockIdx.x * 256 + threadIdx.x;
    if (i < n) g_off[i] += g_bbase[blockIdx.x];
    if (i == 0) g_off[n] = e;
}

// ---------------- CSR fill (atomic-free: uses deg-phase ranks) ---------------
__global__ void fill_kernel(const int* __restrict__ ei, int e, int n) {
    int i = blockIdx.x * blockDim.x + threadIdx.x;
    if (i < e) {
        int d = ei[e + i];
        int s = ei[i];
        if ((unsigned)d < (unsigned)n)
            g_csrc[g_off[d] + g_rank[i]] = s;
    }
}

// ---------------- single-pass softmax + aggregate ----------------------------
__global__ __launch_bounds__(256) void agg_kernel(
    const float* __restrict__ bias, float* __restrict__ out, int n)
{
    int warp = (blockIdx.x * blockDim.x + threadIdx.x) >> 5;
    int lane = threadIdx.x & 31;
    if (warp >= n) return;
    int node = warp;
    int beg = g_off[node], end = g_off[node + 1];

    float adl = (lane < HEADS) ? g_adst[node * HEADS + lane] : 0.f;

    float accx[4], accy[4];
    #pragma unroll
    for (int k = 0; k < 4; k++) { accx[k] = 0.f; accy[k] = 0.f; }
    float s_l = 0.f;               // lane<8: softmax denom for head=lane
    int hsel = lane >> 4;          // 0: even heads, 1: odd heads

    for (int i = beg; i <= end; i++) {
        int src = (i < end) ? g_csrc[i] : node;   // final iter = self loop
        float ex = 0.f;
        if (lane < 8) {
            float ev = g_asrc[src * HEADS + lane] + adl;
            ev = ev > 0.f ? ev : NEG * ev;
            ex = __expf(ev);
            s_l += ex;
        }
        const __half2* hp = (const __half2*)(g_hh + (size_t)src * HID);
        #pragma unroll
        for (int k = 0; k < 4; k++) {
            float exk = __shfl_sync(0xffffffffu, ex, 2 * k + hsel);
            float2 hv = __half22float2(hp[k * 32 + lane]);
            accx[k] = fmaf(exk, hv.x, accx[k]);
            accy[k] = fmaf(exk, hv.y, accy[k]);
        }
    }

    float inv_l = (lane < HEADS) ? __frcp_rn(s_l) : 0.f;
    float resx = 0.f, resy = 0.f;
    #pragma unroll
    for (int k = 0; k < 4; k++) {
        float invk = __shfl_sync(0xffffffffu, inv_l, 2 * k + hsel);
        resx = fmaf(accx[k], invk, resx);
        resy = fmaf(accy[k], invk, resy);
    }
    resx += __shfl_xor_sync(0xffffffffu, resx, 16);
    resy += __shfl_xor_sync(0xffffffffu, resy, 16);
    if (lane < 16) {
        int c = 2 * lane;
        float2 o2 = make_float2(resx * 0.125f + bias[c],
                                resy * 0.125f + bias[c + 1]);
        *(float2*)(out + node * ODIM + c) = o2;
    }
}

// ---------------- launcher ---------------------------------------------------
// gemm_kernel stays at kernel-launch index 3 (the slot ncu captures).
extern "C" void kernel_launch(void* const* d_in, const int* in_sizes, int n_in,
                              void* d_out, int out_size)
{
    const float* x     = (const float*)d_in[0];
    const int*   ei    = (const int*)d_in[1];   // [2, E] — int32 (JAX x64 off)
    const float* W     = (const float*)d_in[3];
    const float* att_s = (const float*)d_in[4];
    const float* att_d = (const float*)d_in[5];
    const float* bias  = (const float*)d_in[6];
    float*       out   = (float*)d_out;

    int n = in_sizes[0] / IN_DIM;
    int e = in_sizes[1] / 2;
    int nb = (n + 255) / 256;
    const int smem_bytes = SMEM_FLOATS * 4;   // 86016 B

    cudaFuncSetAttribute(gemm_kernel,
                         cudaFuncAttributeMaxDynamicSharedMemorySize, smem_bytes);

    zero_kernel<<<nb, 256>>>(W, n);
    deg_kernel<<<(e + 255) / 256, 256>>>(ei, e, n);
    scan_a_kernel<<<nb, 256>>>(n);
    gemm_kernel<<<(n + BM - 1) / BM, 256, smem_bytes>>>(x, att_s, att_d, n);
    scan_b_kernel<<<1, 256>>>(nb);
    scan_c_kernel<<<nb, 256>>>(n, e);
    fill_kernel<<<(e + 255) / 256, 256>>>(ei, e, n);
    agg_kernel<<<(n * 32 + 255) / 256, 256>>>(bias, out, n);
}

// round 12
// speedup vs baseline: 1.3391x; 1.0879x over previous
#include <cuda_runtime.h>
#include <cuda_fp16.h>

#define IN_DIM 128
#define HEADS 8
#define ODIM 32
#define HID 256            // HEADS*ODIM
#define NEG 0.2f
#define NMAX 50000
#define EMAX 800000
#define WELEM (IN_DIM * HID)   // 32768

// GEMM tiling: block 64x256, k-tile 32, warps 4(M) x 2(N), warp tile 16x128
#define BM 64
#define XS_STRIDE 36
#define WS_STRIDE 264
#define XS_FLOATS (64 * XS_STRIDE)                 // 2304
#define WS_FLOATS (32 * WS_STRIDE)                 // 8448
#define BUF_FLOATS (XS_FLOATS + WS_FLOATS)         // 10752
#define SMEM_FLOATS (2 * BUF_FLOATS)               // 84 KB -> 2 CTAs/SM
#define D_STRIDE 260

// ---------------- device scratch (static: no allocation allowed) -------------
__device__ __half g_hh[NMAX * HID];      // 25.6 MB (fp16 messages)
__device__ float  g_asrc[NMAX * HEADS];
__device__ float  g_adst[NMAX * HEADS];
__device__ float  g_wt[WELEM];           // W pre-rounded to tf32 bit pattern
__device__ int    g_deg[NMAX];
__device__ int    g_rank[EMAX];          // edge rank within its dst bucket
__device__ int    g_off[NMAX + 1];
__device__ int    g_csrc[EMAX];
__device__ int    g_bsum[256];
__device__ int    g_bbase[256];

// ---------------- helpers ----------------------------------------------------
__device__ __forceinline__ void cp16(void* dst, const void* src, bool pred) {
    unsigned d = (unsigned)__cvta_generic_to_shared(dst);
    int sz = pred ? 16 : 0;
    asm volatile("cp.async.cg.shared.global [%0], [%1], 16, %2;"
                 :: "r"(d), "l"(src), "r"(sz) : "memory");
}
__device__ __forceinline__ unsigned tf32u(float v) {
    unsigned u;
    asm("cvt.rna.tf32.f32 %0, %1;" : "=r"(u) : "f"(v));
    return u;
}
__device__ __forceinline__ void mma_tf32(float4& d,
    unsigned a0, unsigned a1, unsigned a2, unsigned a3,
    unsigned b0, unsigned b1)
{
    asm volatile(
        "mma.sync.aligned.m16n8k8.row.col.f32.tf32.tf32.f32 "
        "{%0,%1,%2,%3}, {%4,%5,%6,%7}, {%8,%9}, {%0,%1,%2,%3};"
        : "+f"(d.x), "+f"(d.y), "+f"(d.z), "+f"(d.w)
        : "r"(a0), "r"(a1), "r"(a2), "r"(a3), "r"(b0), "r"(b1));
}

// ---------------- zero + W->tf32 pre-convert ---------------------------------
__global__ void zero_kernel(const float* __restrict__ W, int n) {
    int i = blockIdx.x * blockDim.x + threadIdx.x;
    if (i < n) g_deg[i] = 0;
    if (i < WELEM) g_wt[i] = __uint_as_float(tf32u(W[i]));
}

// ---------------- tf32 tensor-core GEMM + fused attention dots ---------------
__global__ void __launch_bounds__(256, 2) gemm_kernel(
    const float* __restrict__ x,
    const float* __restrict__ att_s, const float* __restrict__ att_d, int n)
{
    extern __shared__ float smem[];
    float* xsb[2] = { smem,             smem + BUF_FLOATS };
    float* wsb[2] = { smem + XS_FLOATS, smem + BUF_FLOATS + XS_FLOATS };

    int tid  = threadIdx.x;
    int lane = tid & 31, wid = tid >> 5;
    int g    = lane >> 2, tig = lane & 3;
    int wm   = wid & 3,   wn  = wid >> 2;      // 4(M) x 2(N)
    int row0 = blockIdx.x * BM;

    auto issue = [&](int kt, int b) {
        float* xs = xsb[b];
        float* ws = wsb[b];
        #pragma unroll
        for (int t = 0; t < 2; t++) {
            int q = tid + t * 256;
            int r = q >> 3, k4 = q & 7;
            int grow = row0 + r;
            cp16(xs + r * XS_STRIDE + k4 * 4,
                 x + (size_t)grow * IN_DIM + kt * 32 + k4 * 4, grow < n);
        }
        #pragma unroll
        for (int t = 0; t < 8; t++) {
            int q = tid + t * 256;
            int r = q >> 6, c4 = q & 63;
            cp16(ws + r * WS_STRIDE + c4 * 4,
                 g_wt + (size_t)(kt * 32 + r) * 256 + c4 * 4, true);
        }
        asm volatile("cp.async.commit_group;" ::: "memory");
    };

    float4 acc[16];
    #pragma unroll
    for (int t = 0; t < 16; t++) acc[t] = make_float4(0.f, 0.f, 0.f, 0.f);

    issue(0, 0);

    #pragma unroll
    for (int kt = 0; kt < 4; kt++) {
        if (kt < 3) issue(kt + 1, (kt + 1) & 1);
        if (kt < 3) asm volatile("cp.async.wait_group 1;" ::: "memory");
        else        asm volatile("cp.async.wait_group 0;" ::: "memory");
        __syncthreads();

        const float* xs = xsb[kt & 1];
        const float* ws = wsb[kt & 1];
        #pragma unroll
        for (int ks = 0; ks < 4; ks++) {
            int kk = ks * 8;
            const float* xa = xs + (wm * 16) * XS_STRIDE + kk;
            unsigned a0 = tf32u(xa[g * XS_STRIDE + tig]);
            unsigned a1 = tf32u(xa[(g + 8) * XS_STRIDE + tig]);
            unsigned a2 = tf32u(xa[g * XS_STRIDE + tig + 4]);
            unsigned a3 = tf32u(xa[(g + 8) * XS_STRIDE + tig + 4]);
            const float* wb = ws + kk * WS_STRIDE + wn * 128 + g;
            #pragma unroll
            for (int nc = 0; nc < 4; nc++) {
                unsigned bq[8];
                #pragma unroll
                for (int j = 0; j < 4; j++) {
                    int nt = nc * 4 + j;
                    bq[2 * j]     = __float_as_uint(wb[tig * WS_STRIDE + nt * 8]);
                    bq[2 * j + 1] = __float_as_uint(wb[(tig + 4) * WS_STRIDE + nt * 8]);
                }
                #pragma unroll
                for (int j = 0; j < 4; j++)
                    mma_tf32(acc[nc * 4 + j], a0, a1, a2, a3, bq[2 * j], bq[2 * j + 1]);
            }
        }
        __syncthreads();
    }

    // ---- epilogue: D -> smem row-major, then h + dots -----------------------
    float* Dsm = smem;
    {
        int rbase = wm * 16;
        int cbase = wn * 128 + tig * 2;
        #pragma unroll
        for (int nt = 0; nt < 16; nt++) {
            int c = cbase + nt * 8;
            *(float2*)(Dsm + (rbase + g) * D_STRIDE + c)     = make_float2(acc[nt].x, acc[nt].y);
            *(float2*)(Dsm + (rbase + g + 8) * D_STRIDE + c) = make_float2(acc[nt].z, acc[nt].w);
        }
    }
    __syncthreads();

    {
        int row  = tid >> 2, part = tid & 3;
        int grow = row0 + row;
        if (grow < n) {
            int c0 = part * 64;
            float d[64];
            #pragma unroll
            for (int i = 0; i < 16; i++)
                *(float4*)(d + i * 4) = *(const float4*)(Dsm + row * D_STRIDE + c0 + i * 4);

            __half2 hv[4];
            #pragma unroll
            for (int i = 0; i < 8; i++) {
                #pragma unroll
                for (int p = 0; p < 4; p++)
                    hv[p] = __floats2half2_rn(d[i * 8 + 2 * p], d[i * 8 + 2 * p + 1]);
                *(uint4*)(g_hh + (size_t)grow * HID + c0 + i * 8) = *(uint4*)hv;
            }

            float s0 = 0.f, s1 = 0.f, t0 = 0.f, t1 = 0.f;
            #pragma unroll
            for (int j = 0; j < 32; j++) {
                s0 += d[j]      * att_s[c0 + j];
                t0 += d[j]      * att_d[c0 + j];
                s1 += d[j + 32] * att_s[c0 + 32 + j];
                t1 += d[j + 32] * att_d[c0 + 32 + j];
            }
            int h0 = 2 * part;
            g_asrc[grow * HEADS + h0]     = s0;
            g_asrc[grow * HEADS + h0 + 1] = s1;
            g_adst[grow * HEADS + h0]     = t0;
            g_adst[grow * HEADS + h0 + 1] = t1;
        }
    }
}

// ---------------- degree histogram + per-edge rank ---------------------------
__global__ void deg_kernel(const int* __restrict__ ei, int e, int n) {
    int i = blockIdx.x * blockDim.x + threadIdx.x;
    if (i < e) {
        int d = ei[e + i];   // dst row of edge_index [2, E]
        int r = 0;
        if ((unsigned)d < (unsigned)n) r = atomicAdd(&g_deg[d], 1);
        g_rank[i] = r;
    }
}

// ---------------- 3-kernel exclusive scan ------------------------------------
__device__ __forceinline__ int block_scan_incl(int v, int tid) {
    __shared__ int wsum[8];
    int lane = tid & 31, w = tid >> 5;
    int x = v;
    #pragma unroll
    for (int o = 1; o < 32; o <<= 1) {
        int y = __shfl_up_sync(0xffffffffu, x, o);
        if (lane >= o) x += y;
    }
    if (lane == 31) wsum[w] = x;
    __syncthreads();
    if (tid < 8) {
        int y = wsum[tid];
        #pragma unroll
        for (int o = 1; o < 8; o <<= 1) {
            int z = __shfl_up_sync(0xffu, y, o);
            if (tid >= o) y += z;
        }
        wsum[tid] = y;
    }
    __syncthreads();
    int base = (w > 0) ? wsum[w - 1] : 0;
    return x + base;
}

__global__ void scan_a_kernel(int n) {
    int i = blockIdx.x * 256 + threadIdx.x;
    int v = (i < n) ? g_deg[i] : 0;
    int incl = block_scan_incl(v, threadIdx.x);
    if (i < n) g_off[i] = incl - v;
    if (threadIdx.x == 255) g_bsum[blockIdx.x] = incl;
}

__global__ void scan_b_kernel(int nb) {
    int t = threadIdx.x;
    int v = (t < nb) ? g_bsum[t] : 0;
    int incl = block_scan_incl(v, t);
    g_bbase[t] = incl - v;
}

__global__ void scan_c_kernel(int n, int e) {
    int i = blockIdx.x * 256 + threadIdx.x;
    if (i < n) g_off[i] += g_bbase[blockIdx.x];
    if (i == 0) g_off[n] = e;
}

// ---------------- CSR fill (atomic-free: uses deg-phase ranks) ---------------
__global__ void fill_kernel(const int* __restrict__ ei, int e, int n) {
    int i = blockIdx.x * blockDim.x + threadIdx.x;
    if (i < e) {
        int d = ei[e + i];
        int s = ei[i];
        if ((unsigned)d < (unsigned)n)
            g_csrc[g_off[d] + g_rank[i]] = s;
    }
}

// ---------------- single-pass softmax + aggregate ----------------------------
__global__ __launch_bounds__(256) void agg_kernel(
    const float* __restrict__ bias, float* __restrict__ out, int n)
{
    int warp = (blockIdx.x * blockDim.x + threadIdx.x) >> 5;
    int lane = threadIdx.x & 31;
    if (warp >= n) return;
    int node = warp;
    int beg = g_off[node], end = g_off[node + 1];

    float adl = (lane < HEADS) ? g_adst[node * HEADS + lane] : 0.f;

    float accx[4], accy[4];
    #pragma unroll
    for (int k = 0; k < 4; k++) { accx[k] = 0.f; accy[k] = 0.f; }
    float s_l = 0.f;               // lane<8: softmax denom for head=lane
    int hsel = lane >> 4;          // 0: even heads, 1: odd heads

    for (int i = beg; i <= end; i++) {
        int src = (i < end) ? g_csrc[i] : node;   // final iter = self loop
        float ex = 0.f;
        if (lane < 8) {
            float ev = g_asrc[src * HEADS + lane] + adl;
            ev = ev > 0.f ? ev : NEG * ev;
            ex = __expf(ev);
            s_l += ex;
        }
        const __half2* hp = (const __half2*)(g_hh + (size_t)src * HID);
        #pragma unroll
        for (int k = 0; k < 4; k++) {
            float exk = __shfl_sync(0xffffffffu, ex, 2 * k + hsel);
            float2 hv = __half22float2(hp[k * 32 + lane]);
            accx[k] = fmaf(exk, hv.x, accx[k]);
            accy[k] = fmaf(exk, hv.y, accy[k]);
        }
    }

    float inv_l = (lane < HEADS) ? __frcp_rn(s_l) : 0.f;
    float resx = 0.f, resy = 0.f;
    #pragma unroll
    for (int k = 0; k < 4; k++) {
        float invk = __shfl_sync(0xffffffffu, inv_l, 2 * k + hsel);
        resx = fmaf(accx[k], invk, resx);
        resy = fmaf(accy[k], invk, resy);
    }
    resx += __shfl_xor_sync(0xffffffffu, resx, 16);
    resy += __shfl_xor_sync(0xffffffffu, resy, 16);
    if (lane < 16) {
        int c = 2 * lane;
        float2 o2 = make_float2(resx * 0.125f + bias[c],
                                resy * 0.125f + bias[c + 1]);
        *(float2*)(out + node * ODIM + c) = o2;
    }
}

// ---------------- launcher: fork/join stream overlap -------------------------
// CSR build (deg/scan/fill) runs on a side stream concurrently with the GEMM.
// Fork/join via events is the documented multi-stream graph-capture pattern.
// Stream/events are created per call and intentionally not destroyed:
// kernel_launch runs only a handful of times (correctness + capture); graph
// replays do not re-enter this function. Captured work is identical per call.
extern "C" void kernel_launch(void* const* d_in, const int* in_sizes, int n_in,
                              void* d_out, int out_size)
{
    const float* x     = (const float*)d_in[0];
    const int*   ei    = (const int*)d_in[1];   // [2, E] — int32 (JAX x64 off)
    const float* W     = (const float*)d_in[3];
    const float* att_s = (const float*)d_in[4];
    const float* att_d = (const float*)d_in[5];
    const float* bias  = (const float*)d_in[6];
    float*       out   = (float*)d_out;

    int n = in_sizes[0] / IN_DIM;
    int e = in_sizes[1] / 2;
    int nb = (n + 255) / 256;
    const int smem_bytes = SMEM_FLOATS * 4;   // 86016 B

    cudaFuncSetAttribute(gemm_kernel,
                         cudaFuncAttributeMaxDynamicSharedMemorySize, smem_bytes);

    cudaStream_t s1;
    cudaEvent_t ev_fork, ev_join;
    cudaStreamCreateWithFlags(&s1, cudaStreamNonBlocking);
    cudaEventCreateWithFlags(&ev_fork, cudaEventDisableTiming);
    cudaEventCreateWithFlags(&ev_join, cudaEventDisableTiming);

    // main stream: zero (g_deg + W cvt) first — both branches depend on it
    zero_kernel<<<nb, 256, 0, 0>>>(W, n);
    cudaEventRecord(ev_fork, 0);

    // side stream: CSR build chain
    cudaStreamWaitEvent(s1, ev_fork, 0);
    deg_kernel<<<(e + 255) / 256, 256, 0, s1>>>(ei, e, n);
    scan_a_kernel<<<nb, 256, 0, s1>>>(n);
    scan_b_kernel<<<1, 256, 0, s1>>>(nb);
    scan_c_kernel<<<nb, 256, 0, s1>>>(n, e);
    fill_kernel<<<(e + 255) / 256, 256, 0, s1>>>(ei, e, n);
    cudaEventRecord(ev_join, s1);

    // main stream: GEMM concurrently with CSR build
    gemm_kernel<<<(n + BM - 1) / BM, 256, smem_bytes, 0>>>(x, att_s, att_d, n);

    // join, then aggregate
    cudaStreamWaitEvent(0, ev_join, 0);
    agg_kernel<<<(n * 32 + 255) / 256, 256, 0, 0>>>(bias, out, n);
}

// round 13
// speedup vs baseline: 1.4198x; 1.0602x over previous
#include <cuda_runtime.h>
#include <cuda_fp16.h>

#define IN_DIM 128
#define HEADS 8
#define ODIM 32
#define HID 256            // HEADS*ODIM
#define NEG 0.2f
#define NMAX 50000
#define EMAX 800000
#define WELEM (IN_DIM * HID)   // 32768

// GEMM tiling: block 64x256, k-tile 32, warps 4(M) x 2(N), warp tile 16x128
#define BM 64
#define XS_STRIDE 36
#define WS_STRIDE 264
#define XS_FLOATS (64 * XS_STRIDE)                 // 2304
#define WS_FLOATS (32 * WS_STRIDE)                 // 8448
#define BUF_FLOATS (XS_FLOATS + WS_FLOATS)         // 10752
#define SMEM_FLOATS (2 * BUF_FLOATS)               // 84 KB -> 2 CTAs/SM
#define D_STRIDE 260

// ---------------- device scratch (static: no allocation allowed) -------------
__device__ __half g_hh[NMAX * HID];      // 25.6 MB (fp16 messages)
__device__ float  g_asrc[NMAX * HEADS];
__device__ float  g_adst[NMAX * HEADS];
__device__ float  g_wt[WELEM];           // W pre-rounded to tf32 bit pattern
__device__ int    g_deg[NMAX];
__device__ int    g_rank[EMAX];          // edge rank within its dst bucket
__device__ int    g_off[NMAX + 1];
__device__ int    g_csrc[EMAX];
__device__ int    g_bsum[256];
__device__ int    g_bbase[256];

// ---------------- helpers ----------------------------------------------------
__device__ __forceinline__ void cp16(void* dst, const void* src, bool pred) {
    unsigned d = (unsigned)__cvta_generic_to_shared(dst);
    int sz = pred ? 16 : 0;
    asm volatile("cp.async.cg.shared.global [%0], [%1], 16, %2;"
                 :: "r"(d), "l"(src), "r"(sz) : "memory");
}
__device__ __forceinline__ unsigned tf32u(float v) {
    unsigned u;
    asm("cvt.rna.tf32.f32 %0, %1;" : "=r"(u) : "f"(v));
    return u;
}
__device__ __forceinline__ void mma_tf32(float4& d,
    unsigned a0, unsigned a1, unsigned a2, unsigned a3,
    unsigned b0, unsigned b1)
{
    asm volatile(
        "mma.sync.aligned.m16n8k8.row.col.f32.tf32.tf32.f32 "
        "{%0,%1,%2,%3}, {%4,%5,%6,%7}, {%8,%9}, {%0,%1,%2,%3};"
        : "+f"(d.x), "+f"(d.y), "+f"(d.z), "+f"(d.w)
        : "r"(a0), "r"(a1), "r"(a2), "r"(a3), "r"(b0), "r"(b1));
}

// ---------------- zero + W->tf32 pre-convert ---------------------------------
__global__ void zero_kernel(const float* __restrict__ W, int n) {
    int i = blockIdx.x * blockDim.x + threadIdx.x;
    if (i < n) g_deg[i] = 0;
    if (i < WELEM) g_wt[i] = __uint_as_float(tf32u(W[i]));
}

// ---------------- tf32 tensor-core GEMM + fused attention dots ---------------
__global__ void __launch_bounds__(256, 2) gemm_kernel(
    const float* __restrict__ x,
    const float* __restrict__ att_s, const float* __restrict__ att_d, int n)
{
    extern __shared__ float smem[];
    float* xsb[2] = { smem,             smem + BUF_FLOATS };
    float* wsb[2] = { smem + XS_FLOATS, smem + BUF_FLOATS + XS_FLOATS };

    int tid  = threadIdx.x;
    int lane = tid & 31, wid = tid >> 5;
    int g    = lane >> 2, tig = lane & 3;
    int wm   = wid & 3,   wn  = wid >> 2;      // 4(M) x 2(N)
    int row0 = blockIdx.x * BM;

    auto issue = [&](int kt, int b) {
        float* xs = xsb[b];
        float* ws = wsb[b];
        #pragma unroll
        for (int t = 0; t < 2; t++) {
            int q = tid + t * 256;
            int r = q >> 3, k4 = q & 7;
            int grow = row0 + r;
            cp16(xs + r * XS_STRIDE + k4 * 4,
                 x + (size_t)grow * IN_DIM + kt * 32 + k4 * 4, grow < n);
        }
        #pragma unroll
        for (int t = 0; t < 8; t++) {
            int q = tid + t * 256;
            int r = q >> 6, c4 = q & 63;
            cp16(ws + r * WS_STRIDE + c4 * 4,
                 g_wt + (size_t)(kt * 32 + r) * 256 + c4 * 4, true);
        }
        asm volatile("cp.async.commit_group;" ::: "memory");
    };

    float4 acc[16];
    #pragma unroll
    for (int t = 0; t < 16; t++) acc[t] = make_float4(0.f, 0.f, 0.f, 0.f);

    issue(0, 0);

    #pragma unroll
    for (int kt = 0; kt < 4; kt++) {
        if (kt < 3) issue(kt + 1, (kt + 1) & 1);
        if (kt < 3) asm volatile("cp.async.wait_group 1;" ::: "memory");
        else        asm volatile("cp.async.wait_group 0;" ::: "memory");
        __syncthreads();

        const float* xs = xsb[kt & 1];
        const float* ws = wsb[kt & 1];
        #pragma unroll
        for (int ks = 0; ks < 4; ks++) {
            int kk = ks * 8;
            const float* xa = xs + (wm * 16) * XS_STRIDE + kk;
            unsigned a0 = tf32u(xa[g * XS_STRIDE + tig]);
            unsigned a1 = tf32u(xa[(g + 8) * XS_STRIDE + tig]);
            unsigned a2 = tf32u(xa[g * XS_STRIDE + tig + 4]);
            unsigned a3 = tf32u(xa[(g + 8) * XS_STRIDE + tig + 4]);
            const float* wb = ws + kk * WS_STRIDE + wn * 128 + g;
            #pragma unroll
            for (int nc = 0; nc < 4; nc++) {
                unsigned bq[8];
                #pragma unroll
                for (int j = 0; j < 4; j++) {
                    int nt = nc * 4 + j;
                    bq[2 * j]     = __float_as_uint(wb[tig * WS_STRIDE + nt * 8]);
                    bq[2 * j + 1] = __float_as_uint(wb[(tig + 4) * WS_STRIDE + nt * 8]);
                }
                #pragma unroll
                for (int j = 0; j < 4; j++)
                    mma_tf32(acc[nc * 4 + j], a0, a1, a2, a3, bq[2 * j], bq[2 * j + 1]);
            }
        }
        __syncthreads();
    }

    // ---- epilogue: D -> smem row-major, then h + dots -----------------------
    float* Dsm = smem;
    {
        int rbase = wm * 16;
        int cbase = wn * 128 + tig * 2;
        #pragma unroll
        for (int nt = 0; nt < 16; nt++) {
            int c = cbase + nt * 8;
            *(float2*)(Dsm + (rbase + g) * D_STRIDE + c)     = make_float2(acc[nt].x, acc[nt].y);
            *(float2*)(Dsm + (rbase + g + 8) * D_STRIDE + c) = make_float2(acc[nt].z, acc[nt].w);
        }
    }
    __syncthreads();

    {
        int row  = tid >> 2, part = tid & 3;
        int grow = row0 + row;
        if (grow < n) {
            int c0 = part * 64;
            float d[64];
            #pragma unroll
            for (int i = 0; i < 16; i++)
                *(float4*)(d + i * 4) = *(const float4*)(Dsm + row * D_STRIDE + c0 + i * 4);

            __half2 hv[4];
            #pragma unroll
            for (int i = 0; i < 8; i++) {
                #pragma unroll
                for (int p = 0; p < 4; p++)
                    hv[p] = __floats2half2_rn(d[i * 8 + 2 * p], d[i * 8 + 2 * p + 1]);
                *(uint4*)(g_hh + (size_t)grow * HID + c0 + i * 8) = *(uint4*)hv;
            }

            float s0 = 0.f, s1 = 0.f, t0 = 0.f, t1 = 0.f;
            #pragma unroll
            for (int j = 0; j < 32; j++) {
                s0 += d[j]      * att_s[c0 + j];
                t0 += d[j]      * att_d[c0 + j];
                s1 += d[j + 32] * att_s[c0 + 32 + j];
                t1 += d[j + 32] * att_d[c0 + 32 + j];
            }
            int h0 = 2 * part;
            g_asrc[grow * HEADS + h0]     = s0;
            g_asrc[grow * HEADS + h0 + 1] = s1;
            g_adst[grow * HEADS + h0]     = t0;
            g_adst[grow * HEADS + h0 + 1] = t1;
        }
    }
}

// ---------------- degree histogram + per-edge rank ---------------------------
__global__ void deg_kernel(const int* __restrict__ ei, int e, int n) {
    int i = blockIdx.x * blockDim.x + threadIdx.x;
    if (i < e) {
        int d = ei[e + i];   // dst row of edge_index [2, E]
        int r = 0;
        if ((unsigned)d < (unsigned)n) r = atomicAdd(&g_deg[d], 1);
        g_rank[i] = r;
    }
}

// ---------------- 3-kernel exclusive scan ------------------------------------
__device__ __forceinline__ int block_scan_incl(int v, int tid) {
    __shared__ int wsum[8];
    int lane = tid & 31, w = tid >> 5;
    int x = v;
    #pragma unroll
    for (int o = 1; o < 32; o <<= 1) {
        int y = __shfl_up_sync(0xffffffffu, x, o);
        if (lane >= o) x += y;
    }
    if (lane == 31) wsum[w] = x;
    __syncthreads();
    if (tid < 8) {
        int y = wsum[tid];
        #pragma unroll
        for (int o = 1; o < 8; o <<= 1) {
            int z = __shfl_up_sync(0xffu, y, o);
            if (tid >= o) y += z;
        }
        wsum[tid] = y;
    }
    __syncthreads();
    int base = (w > 0) ? wsum[w - 1] : 0;
    return x + base;
}

__global__ void scan_a_kernel(int n) {
    int i = blockIdx.x * 256 + threadIdx.x;
    int v = (i < n) ? g_deg[i] : 0;
    int incl = block_scan_incl(v, threadIdx.x);
    if (i < n) g_off[i] = incl - v;
    if (threadIdx.x == 255) g_bsum[blockIdx.x] = incl;
}

__global__ void scan_b_kernel(int nb) {
    int t = threadIdx.x;
    int v = (t < nb) ? g_bsum[t] : 0;
    int incl = block_scan_incl(v, t);
    g_bbase[t] = incl - v;
}

__global__ void scan_c_kernel(int n, int e) {
    int i = blockIdx.x * 256 + threadIdx.x;
    if (i < n) g_off[i] += g_bbase[blockIdx.x];
    if (i == 0) g_off[n] = e;
}

// ---------------- CSR fill (atomic-free: uses deg-phase ranks) ---------------
__global__ void fill_kernel(const int* __restrict__ ei, int e, int n) {
    int i = blockIdx.x * blockDim.x + threadIdx.x;
    if (i < e) {
        int d = ei[e + i];
        int s = ei[i];
        if ((unsigned)d < (unsigned)n)
            g_csrc[g_off[d] + g_rank[i]] = s;
    }
}

// ---------------- single-pass softmax + aggregate ----------------------------
// Lane owns head (lane>>2), col octet 8*(lane&3): one LDG.128 per lane covers
// the whole 512B h row per edge. Prefetch of next edge's src/a_src breaks the
// LDG->exp->shfl serial chain.
__global__ __launch_bounds__(256) void agg_kernel(
    const float* __restrict__ bias, float* __restrict__ out, int n)
{
    int warp = (blockIdx.x * blockDim.x + threadIdx.x) >> 5;
    int lane = threadIdx.x & 31;
    if (warp >= n) return;
    int node = warp;
    int beg = g_off[node], end = g_off[node + 1];

    float adl = (lane < HEADS) ? g_adst[node * HEADS + lane] : 0.f;
    int hsel = lane >> 2;          // head this lane accumulates

    float acc[8];
    #pragma unroll
    for (int j = 0; j < 8; j++) acc[j] = 0.f;
    float s_l = 0.f;               // lanes 0-7: softmax denom for head=lane

    // prefetch first edge
    int src_n = (beg < end) ? g_csrc[beg] : node;
    float a_n = (lane < 8) ? g_asrc[src_n * HEADS + lane] : 0.f;

    for (int i = beg; i <= end; i++) {
        int src = src_n;
        float a = a_n;
        if (i < end) {                       // prefetch i+1 (or self loop)
            src_n = (i + 1 < end) ? g_csrc[i + 1] : node;
            a_n = (lane < 8) ? g_asrc[src_n * HEADS + lane] : 0.f;
        }
        float ex = 0.f;
        if (lane < 8) {
            float ev = a + adl;
            ev = ev > 0.f ? ev : NEG * ev;
            ex = __expf(ev);
            s_l += ex;
        }
        float exk = __shfl_sync(0xffffffffu, ex, hsel);
        uint4 hraw = *(const uint4*)(g_hh + (size_t)src * HID + lane * 8);
        const __half2* hh = (const __half2*)&hraw;
        #pragma unroll
        for (int k2 = 0; k2 < 4; k2++) {
            float2 f = __half22float2(hh[k2]);
            acc[2 * k2]     = fmaf(exk, f.x, acc[2 * k2]);
            acc[2 * k2 + 1] = fmaf(exk, f.y, acc[2 * k2 + 1]);
        }
    }

    // normalize per-head, then fold the 8 heads (lanes {q,q+4,...,q+28})
    float inv_l = (lane < 8) ? __frcp_rn(s_l) : 0.f;
    float invk = __shfl_sync(0xffffffffu, inv_l, hsel) * 0.125f;
    #pragma unroll
    for (int j = 0; j < 8; j++) acc[j] *= invk;
    #pragma unroll
    for (int o = 4; o < 32; o <<= 1)
        #pragma unroll
        for (int j = 0; j < 8; j++)
            acc[j] += __shfl_xor_sync(0xffffffffu, acc[j], o);

    if (lane < 4) {
        int c0 = lane * 8;
        float4 o0 = make_float4(acc[0] + bias[c0],     acc[1] + bias[c0 + 1],
                                acc[2] + bias[c0 + 2], acc[3] + bias[c0 + 3]);
        float4 o1 = make_float4(acc[4] + bias[c0 + 4], acc[5] + bias[c0 + 5],
                                acc[6] + bias[c0 + 6], acc[7] + bias[c0 + 7]);
        *(float4*)(out + node * ODIM + c0)     = o0;
        *(float4*)(out + node * ODIM + c0 + 4) = o1;
    }
}

// ---------------- launcher: fork/join stream overlap -------------------------
extern "C" void kernel_launch(void* const* d_in, const int* in_sizes, int n_in,
                              void* d_out, int out_size)
{
    const float* x     = (const float*)d_in[0];
    const int*   ei    = (const int*)d_in[1];   // [2, E] — int32 (JAX x64 off)
    const float* W     = (const float*)d_in[3];
    const float* att_s = (const float*)d_in[4];
    const float* att_d = (const float*)d_in[5];
    const float* bias  = (const float*)d_in[6];
    float*       out   = (float*)d_out;

    int n = in_sizes[0] / IN_DIM;
    int e = in_sizes[1] / 2;
    int nb = (n + 255) / 256;
    const int smem_bytes = SMEM_FLOATS * 4;   // 86016 B

    cudaFuncSetAttribute(gemm_kernel,
                         cudaFuncAttributeMaxDynamicSharedMemorySize, smem_bytes);

    cudaStream_t s1;
    cudaEvent_t ev_fork, ev_join;
    cudaStreamCreateWithFlags(&s1, cudaStreamNonBlocking);
    cudaEventCreateWithFlags(&ev_fork, cudaEventDisableTiming);
    cudaEventCreateWithFlags(&ev_join, cudaEventDisableTiming);

    // main stream: zero (g_deg + W cvt) first — both branches depend on it
    zero_kernel<<<nb, 256, 0, 0>>>(W, n);
    cudaEventRecord(ev_fork, 0);

    // side stream: CSR build chain
    cudaStreamWaitEvent(s1, ev_fork, 0);
    deg_kernel<<<(e + 255) / 256, 256, 0, s1>>>(ei, e, n);
    scan_a_kernel<<<nb, 256, 0, s1>>>(n);
    scan_b_kernel<<<1, 256, 0, s1>>>(nb);
    scan_c_kernel<<<nb, 256, 0, s1>>>(n, e);
    fill_kernel<<<(e + 255) / 256, 256, 0, s1>>>(ei, e, n);
    cudaEventRecord(ev_join, s1);

    // main stream: GEMM concurrently with CSR build
    gemm_kernel<<<(n + BM - 1) / BM, 256, smem_bytes, 0>>>(x, att_s, att_d, n);

    // join, then aggregate
    cudaStreamWaitEvent(0, ev_join, 0);
    agg_kernel<<<(n * 32 + 255) / 256, 256, 0, 0>>>(bias, out, n);
}

// round 14
// speedup vs baseline: 1.5389x; 1.0839x over previous
#include <cuda_runtime.h>
#include <cuda_fp16.h>

#define IN_DIM 128
#define HEADS 8
#define ODIM 32
#define HID 256            // HEADS*ODIM
#define NEG 0.2f
#define NMAX 50000
#define EMAX 800000
#define WELEM (IN_DIM * HID)   // 32768

// GEMM tiling: block 64x256, k-tile 32, warps 4(M) x 2(N), warp tile 16x128
#define BM 64
#define XS_STRIDE 36
#define WS_STRIDE 264
#define XS_FLOATS (64 * XS_STRIDE)                 // 2304
#define WS_FLOATS (32 * WS_STRIDE)                 // 8448
#define BUF_FLOATS (XS_FLOATS + WS_FLOATS)         // 10752
#define SMEM_FLOATS (2 * BUF_FLOATS)               // 84 KB -> 2 CTAs/SM
#define D_STRIDE 260

// ---------------- device scratch (static: no allocation allowed) -------------
__device__ __half g_hh[NMAX * HID];      // 25.6 MB (fp16 messages)
__device__ float  g_asrc[NMAX * HEADS];
__device__ float  g_adst[NMAX * HEADS];
__device__ float  g_wt[WELEM];           // W pre-rounded to tf32 bit pattern
__device__ int    g_deg[NMAX];
__device__ int    g_rank[EMAX];          // edge rank within its dst bucket
__device__ int    g_off[NMAX + 1];
__device__ int    g_csrc[EMAX];
__device__ int    g_bsum[256];
__device__ int    g_bbase[256];

// ---------------- helpers ----------------------------------------------------
__device__ __forceinline__ void cp16(void* dst, const void* src, bool pred) {
    unsigned d = (unsigned)__cvta_generic_to_shared(dst);
    int sz = pred ? 16 : 0;
    asm volatile("cp.async.cg.shared.global [%0], [%1], 16, %2;"
                 :: "r"(d), "l"(src), "r"(sz) : "memory");
}
__device__ __forceinline__ unsigned tf32u(float v) {
    unsigned u;
    asm("cvt.rna.tf32.f32 %0, %1;" : "=r"(u) : "f"(v));
    return u;
}
__device__ __forceinline__ void mma_tf32(float4& d,
    unsigned a0, unsigned a1, unsigned a2, unsigned a3,
    unsigned b0, unsigned b1)
{
    asm volatile(
        "mma.sync.aligned.m16n8k8.row.col.f32.tf32.tf32.f32 "
        "{%0,%1,%2,%3}, {%4,%5,%6,%7}, {%8,%9}, {%0,%1,%2,%3};"
        : "+f"(d.x), "+f"(d.y), "+f"(d.z), "+f"(d.w)
        : "r"(a0), "r"(a1), "r"(a2), "r"(a3), "r"(b0), "r"(b1));
}

// ---------------- zero + W->tf32 pre-convert ---------------------------------
__global__ void zero_kernel(const float* __restrict__ W, int n) {
    int i = blockIdx.x * blockDim.x + threadIdx.x;
    if (i < n) g_deg[i] = 0;
    if (i < WELEM) g_wt[i] = __uint_as_float(tf32u(W[i]));
}

// ---------------- tf32 tensor-core GEMM + fused attention dots ---------------
__global__ void __launch_bounds__(256, 2) gemm_kernel(
    const float* __restrict__ x,
    const float* __restrict__ att_s, const float* __restrict__ att_d, int n)
{
    extern __shared__ float smem[];
    float* xsb[2] = { smem,             smem + BUF_FLOATS };
    float* wsb[2] = { smem + XS_FLOATS, smem + BUF_FLOATS + XS_FLOATS };

    int tid  = threadIdx.x;
    int lane = tid & 31, wid = tid >> 5;
    int g    = lane >> 2, tig = lane & 3;
    int wm   = wid & 3,   wn  = wid >> 2;      // 4(M) x 2(N)
    int row0 = blockIdx.x * BM;

    auto issue = [&](int kt, int b) {
        float* xs = xsb[b];
        float* ws = wsb[b];
        #pragma unroll
        for (int t = 0; t < 2; t++) {
            int q = tid + t * 256;
            int r = q >> 3, k4 = q & 7;
            int grow = row0 + r;
            cp16(xs + r * XS_STRIDE + k4 * 4,
                 x + (size_t)grow * IN_DIM + kt * 32 + k4 * 4, grow < n);
        }
        #pragma unroll
        for (int t = 0; t < 8; t++) {
            int q = tid + t * 256;
            int r = q >> 6, c4 = q & 63;
            cp16(ws + r * WS_STRIDE + c4 * 4,
                 g_wt + (size_t)(kt * 32 + r) * 256 + c4 * 4, true);
        }
        asm volatile("cp.async.commit_group;" ::: "memory");
    };

    float4 acc[16];
    #pragma unroll
    for (int t = 0; t < 16; t++) acc[t] = make_float4(0.f, 0.f, 0.f, 0.f);

    issue(0, 0);

    #pragma unroll
    for (int kt = 0; kt < 4; kt++) {
        if (kt < 3) issue(kt + 1, (kt + 1) & 1);
        if (kt < 3) asm volatile("cp.async.wait_group 1;" ::: "memory");
        else        asm volatile("cp.async.wait_group 0;" ::: "memory");
        __syncthreads();

        const float* xs = xsb[kt & 1];
        const float* ws = wsb[kt & 1];
        #pragma unroll
        for (int ks = 0; ks < 4; ks++) {
            int kk = ks * 8;
            const float* xa = xs + (wm * 16) * XS_STRIDE + kk;
            unsigned a0 = tf32u(xa[g * XS_STRIDE + tig]);
            unsigned a1 = tf32u(xa[(g + 8) * XS_STRIDE + tig]);
            unsigned a2 = tf32u(xa[g * XS_STRIDE + tig + 4]);
            unsigned a3 = tf32u(xa[(g + 8) * XS_STRIDE + tig + 4]);
            const float* wb = ws + kk * WS_STRIDE + wn * 128 + g;
            #pragma unroll
            for (int nc = 0; nc < 4; nc++) {
                unsigned bq[8];
                #pragma unroll
                for (int j = 0; j < 4; j++) {
                    int nt = nc * 4 + j;
                    bq[2 * j]     = __float_as_uint(wb[tig * WS_STRIDE + nt * 8]);
                    bq[2 * j + 1] = __float_as_uint(wb[(tig + 4) * WS_STRIDE + nt * 8]);
                }
                #pragma unroll
                for (int j = 0; j < 4; j++)
                    mma_tf32(acc[nc * 4 + j], a0, a1, a2, a3, bq[2 * j], bq[2 * j + 1]);
            }
        }
        __syncthreads();
    }

    // ---- epilogue: D -> smem row-major, then h + dots -----------------------
    float* Dsm = smem;
    {
        int rbase = wm * 16;
        int cbase = wn * 128 + tig * 2;
        #pragma unroll
        for (int nt = 0; nt < 16; nt++) {
            int c = cbase + nt * 8;
            *(float2*)(Dsm + (rbase + g) * D_STRIDE + c)     = make_float2(acc[nt].x, acc[nt].y);
            *(float2*)(Dsm + (rbase + g + 8) * D_STRIDE + c) = make_float2(acc[nt].z, acc[nt].w);
        }
    }
    __syncthreads();

    {
        int row  = tid >> 2, part = tid & 3;
        int grow = row0 + row;
        if (grow < n) {
            int c0 = part * 64;
            float d[64];
            #pragma unroll
            for (int i = 0; i < 16; i++)
                *(float4*)(d + i * 4) = *(const float4*)(Dsm + row * D_STRIDE + c0 + i * 4);

            __half2 hv[4];
            #pragma unroll
            for (int i = 0; i < 8; i++) {
                #pragma unroll
                for (int p = 0; p < 4; p++)
                    hv[p] = __floats2half2_rn(d[i * 8 + 2 * p], d[i * 8 + 2 * p + 1]);
                *(uint4*)(g_hh + (size_t)grow * HID + c0 + i * 8) = *(uint4*)hv;
            }

            float s0 = 0.f, s1 = 0.f, t0 = 0.f, t1 = 0.f;
            #pragma unroll
            for (int j = 0; j < 32; j++) {
                s0 += d[j]      * att_s[c0 + j];
                t0 += d[j]      * att_d[c0 + j];
                s1 += d[j + 32] * att_s[c0 + 32 + j];
                t1 += d[j + 32] * att_d[c0 + 32 + j];
            }
            int h0 = 2 * part;
            g_asrc[grow * HEADS + h0]     = s0;
            g_asrc[grow * HEADS + h0 + 1] = s1;
            g_adst[grow * HEADS + h0]     = t0;
            g_adst[grow * HEADS + h0 + 1] = t1;
        }
    }
}

// ---------------- degree histogram + per-edge rank ---------------------------
__global__ void deg_kernel(const int* __restrict__ ei, int e, int n) {
    int i = blockIdx.x * blockDim.x + threadIdx.x;
    if (i < e) {
        int d = ei[e + i];   // dst row of edge_index [2, E]
        int r = 0;
        if ((unsigned)d < (unsigned)n) r = atomicAdd(&g_deg[d], 1);
        g_rank[i] = r;
    }
}

// ---------------- 3-kernel exclusive scan ------------------------------------
__device__ __forceinline__ int block_scan_incl(int v, int tid) {
    __shared__ int wsum[8];
    int lane = tid & 31, w = tid >> 5;
    int x = v;
    #pragma unroll
    for (int o = 1; o < 32; o <<= 1) {
        int y = __shfl_up_sync(0xffffffffu, x, o);
        if (lane >= o) x += y;
    }
    if (lane == 31) wsum[w] = x;
    __syncthreads();
    if (tid < 8) {
        int y = wsum[tid];
        #pragma unroll
        for (int o = 1; o < 8; o <<= 1) {
            int z = __shfl_up_sync(0xffu, y, o);
            if (tid >= o) y += z;
        }
        wsum[tid] = y;
    }
    __syncthreads();
    int base = (w > 0) ? wsum[w - 1] : 0;
    return x + base;
}

__global__ void scan_a_kernel(int n) {
    int i = blockIdx.x * 256 + threadIdx.x;
    int v = (i < n) ? g_deg[i] : 0;
    int incl = block_scan_incl(v, threadIdx.x);
    if (i < n) g_off[i] = incl - v;
    if (threadIdx.x == 255) g_bsum[blockIdx.x] = incl;
}

__global__ void scan_b_kernel(int nb) {
    int t = threadIdx.x;
    int v = (t < nb) ? g_bsum[t] : 0;
    int incl = block_scan_incl(v, t);
    g_bbase[t] = incl - v;
}

__global__ void scan_c_kernel(int n, int e) {
    int i = blockIdx.x * 256 + threadIdx.x;
    if (i < n) g_off[i] += g_bbase[blockIdx.x];
    if (i == 0) g_off[n] = e;
}

// ---------------- CSR fill (atomic-free: uses deg-phase ranks) ---------------
__global__ void fill_kernel(const int* __restrict__ ei, int e, int n) {
    int i = blockIdx.x * blockDim.x + threadIdx.x;
    if (i < e) {
        int d = ei[e + i];
        int s = ei[i];
        if ((unsigned)d < (unsigned)n)
            g_csrc[g_off[d] + g_rank[i]] = s;
    }
}

// ---------------- single-pass softmax + aggregate (4-edge groups) ------------
// Logit layout: lane = (edge-slot lane>>3, head lane&7) -> one coalesced LDG
// covers a_src for 4 edges. All 4 h-rows loaded back-to-back (MLP 4-5) before
// any FMA. Accumulator layout: lane owns head lane>>2, col octet 8*(lane&3).
__global__ __launch_bounds__(256) void agg_kernel(
    const float* __restrict__ bias, float* __restrict__ out, int n)
{
    int warp = (blockIdx.x * blockDim.x + threadIdx.x) >> 5;
    int lane = threadIdx.x & 31;
    if (warp >= n) return;
    int node = warp;
    int beg = g_off[node];
    int cnt = g_off[node + 1] - beg + 1;     // edges + self loop

    int eslot = lane >> 3, head8 = lane & 7; // logit role
    int hsel  = lane >> 2;                   // accumulation head

    float adl = g_adst[node * HEADS + head8];

    float acc[8];
    #pragma unroll
    for (int j = 0; j < 8; j++) acc[j] = 0.f;
    float s_part = 0.f;                      // partial denom for head8

    for (int base = 0; base < cnt; base += 4) {
        int pos = base + eslot;
        bool valid = pos < cnt;
        int src_e = (pos < cnt - 1) ? g_csrc[beg + pos] : node;
        float a = g_asrc[src_e * HEADS + head8];
        float ev = a + adl;
        ev = ev > 0.f ? ev : NEG * ev;
        float ex = valid ? __expf(ev) : 0.f;
        s_part += ex;

        int   sj[4];
        float exj[4];
        #pragma unroll
        for (int j = 0; j < 4; j++) {
            sj[j]  = __shfl_sync(0xffffffffu, src_e, j * 8);
            exj[j] = __shfl_sync(0xffffffffu, ex, j * 8 + hsel);
        }
        uint4 hr[4];
        #pragma unroll
        for (int j = 0; j < 4; j++)
            hr[j] = *(const uint4*)(g_hh + (size_t)sj[j] * HID + lane * 8);
        #pragma unroll
        for (int j = 0; j < 4; j++) {
            const __half2* hh = (const __half2*)&hr[j];
            #pragma unroll
            for (int k2 = 0; k2 < 4; k2++) {
                float2 f = __half22float2(hh[k2]);
                acc[2 * k2]     = fmaf(exj[j], f.x, acc[2 * k2]);
                acc[2 * k2 + 1] = fmaf(exj[j], f.y, acc[2 * k2 + 1]);
            }
        }
    }

    // fold the 4 edge-slot groups' denominators (lanes with same head8)
    s_part += __shfl_xor_sync(0xffffffffu, s_part, 8);
    s_part += __shfl_xor_sync(0xffffffffu, s_part, 16);
    float inv_l = __frcp_rn(s_part);         // every lane: inv for head8
    float invk = __shfl_sync(0xffffffffu, inv_l, hsel) * 0.125f;
    #pragma unroll
    for (int j = 0; j < 8; j++) acc[j] *= invk;
    #pragma unroll
    for (int o = 4; o < 32; o <<= 1)
        #pragma unroll
        for (int j = 0; j < 8; j++)
            acc[j] += __shfl_xor_sync(0xffffffffu, acc[j], o);

    if (lane < 4) {
        int c0 = lane * 8;
        float4 o0 = make_float4(acc[0] + bias[c0],     acc[1] + bias[c0 + 1],
                                acc[2] + bias[c0 + 2], acc[3] + bias[c0 + 3]);
        float4 o1 = make_float4(acc[4] + bias[c0 + 4], acc[5] + bias[c0 + 5],
                                acc[6] + bias[c0 + 6], acc[7] + bias[c0 + 7]);
        *(float4*)(out + node * ODIM + c0)     = o0;
        *(float4*)(out + node * ODIM + c0 + 4) = o1;
    }
}

// ---------------- launcher: fork/join stream overlap -------------------------
extern "C" void kernel_launch(void* const* d_in, const int* in_sizes, int n_in,
                              void* d_out, int out_size)
{
    const float* x     = (const float*)d_in[0];
    const int*   ei    = (const int*)d_in[1];   // [2, E] — int32 (JAX x64 off)
    const float* W     = (const float*)d_in[3];
    const float* att_s = (const float*)d_in[4];
    const float* att_d = (const float*)d_in[5];
    const float* bias  = (const float*)d_in[6];
    float*       out   = (float*)d_out;

    int n = in_sizes[0] / IN_DIM;
    int e = in_sizes[1] / 2;
    int nb = (n + 255) / 256;
    const int smem_bytes = SMEM_FLOATS * 4;   // 86016 B

    cudaFuncSetAttribute(gemm_kernel,
                         cudaFuncAttributeMaxDynamicSharedMemorySize, smem_bytes);

    cudaStream_t s1;
    cudaEvent_t ev_fork, ev_join;
    cudaStreamCreateWithFlags(&s1, cudaStreamNonBlocking);
    cudaEventCreateWithFlags(&ev_fork, cudaEventDisableTiming);
    cudaEventCreateWithFlags(&ev_join, cudaEventDisableTiming);

    // main stream: zero (g_deg + W cvt) first — both branches depend on it
    zero_kernel<<<nb, 256, 0, 0>>>(W, n);
    cudaEventRecord(ev_fork, 0);

    // side stream: CSR build chain
    cudaStreamWaitEvent(s1, ev_fork, 0);
    deg_kernel<<<(e + 255) / 256, 256, 0, s1>>>(ei, e, n);
    scan_a_kernel<<<nb, 256, 0, s1>>>(n);
    scan_b_kernel<<<1, 256, 0, s1>>>(nb);
    scan_c_kernel<<<nb, 256, 0, s1>>>(n, e);
    fill_kernel<<<(e + 255) / 256, 256, 0, s1>>>(ei, e, n);
    cudaEventRecord(ev_join, s1);

    // main stream: GEMM concurrently with CSR build
    gemm_kernel<<<(n + BM - 1) / BM, 256, smem_bytes, 0>>>(x, att_s, att_d, n);

    // join, then aggregate
    cudaStreamWaitEvent(0, ev_join, 0);
    agg_kernel<<<(n * 32 + 255) / 256, 256, 0, 0>>>(bias, out, n);
}